// round 4
// baseline (speedup 1.0000x reference)
#include <cuda_runtime.h>
#include <math.h>

#define LL 2
#define DD 1024
#define HH 16
#define DHH 64
#define DFF 4096
#define BB 2
#define TT 2048
#define OV 4096
#define BT (BB*TT)   // 4096

// ---------------- scratch (device globals; no runtime allocation) ----------------
__device__ float g_x [BT*DD];
__device__ float g_h [BT*DD];
__device__ float g_q [BT*DD];
__device__ float g_k [BT*DD];
__device__ float g_v [BT*DD];
__device__ float g_o [BT*DD];
__device__ float g_ff[BT*DFF];
__device__ float g_S [(size_t)BB*HH*TT*TT];   // 512 MB score / prob scratch
__device__ float g_cos[TT*32];
__device__ float g_sin[TT*32];

// ---------------- RoPE trig tables (double precision; fast-math-proof) ----------------
__global__ void trig_kernel(float* __restrict__ ct, float* __restrict__ st) {
    int i = blockIdx.x * 256 + threadIdx.x;
    if (i >= TT * 32) return;
    int t = i >> 5, p = i & 31;
    // inv_freq = 10000^{-(2p)/64}; compute in double, round to fp32 like the reference
    double inv = exp2(-13.287712379549449 * ((double)(2 * p) * (1.0 / 64.0)));
    float invf = (float)inv;
    float angf = (float)((double)t * (double)invf);   // == fp32 multiply rounding
    double c, s;
    sincos((double)angf, &s, &c);                     // exact trig of the fp32 angle
    ct[i] = (float)c;
    st[i] = (float)s;
}

// ---------------- embedding ----------------
__global__ void embed_kernel(const int* __restrict__ act, const int* __restrict__ obs,
                             const float* __restrict__ aemb, const float* __restrict__ oemb,
                             const float* __restrict__ temb, float* __restrict__ x) {
    int idx = blockIdx.x * blockDim.x + threadIdx.x;
    if (idx >= BT * DD) return;
    int r = idx / DD, d = idx % DD;
    x[idx] = aemb[(size_t)act[r] * DD + d] + temb[d]
           + oemb[(size_t)obs[r] * DD + d] + temb[DD + d];
}

// ---------------- layernorm (one block per row, 256 threads) ----------------
__global__ void ln_kernel(const float* __restrict__ x, const float* __restrict__ g,
                          const float* __restrict__ b, float* __restrict__ y) {
    int r = blockIdx.x;
    const float* xr = x + (size_t)r * DD;
    float v[4];
    float s = 0.f, ss = 0.f;
#pragma unroll
    for (int i = 0; i < 4; i++) {
        float t = xr[threadIdx.x + i * 256];
        v[i] = t; s += t; ss += t * t;
    }
#pragma unroll
    for (int o = 16; o > 0; o >>= 1) {
        s  += __shfl_xor_sync(0xffffffffu, s,  o);
        ss += __shfl_xor_sync(0xffffffffu, ss, o);
    }
    __shared__ float rs[8], rss[8];
    int w = threadIdx.x >> 5;
    if ((threadIdx.x & 31) == 0) { rs[w] = s; rss[w] = ss; }
    __syncthreads();
    if (threadIdx.x == 0) {
        float a = 0.f, c = 0.f;
#pragma unroll
        for (int i = 0; i < 8; i++) { a += rs[i]; c += rss[i]; }
        rs[0] = a; rss[0] = c;
    }
    __syncthreads();
    float mean = rs[0] * (1.f / DD);
    float var  = rss[0] * (1.f / DD) - mean * mean;
    float inv  = rsqrtf(var + 1e-5f);
    float* yr = y + (size_t)r * DD;
#pragma unroll
    for (int i = 0; i < 4; i++) {
        int d = threadIdx.x + i * 256;
        yr[d] = (v[i] - mean) * inv * g[d] + b[d];
    }
}

// ---------------- SGEMM: C[M,N] = A[M,K] @ B[K,N] + bias, epilogue variants ----------------
// EPI: 0 = bias only, 1 = bias + exact GELU, 2 = bias + residual add
template <int EPI>
__global__ __launch_bounds__(256)
void sgemm_kernel(const float* __restrict__ A, const float* __restrict__ Bm,
                  const float* __restrict__ bias, const float* __restrict__ R,
                  float* __restrict__ C, int M, int N, int K) {
    __shared__ float As[8][128];
    __shared__ float Bs[8][128];
    int tid = threadIdx.x;
    int bm = blockIdx.y << 7, bn = blockIdx.x << 7;
    int arow = tid >> 1, acol = (tid & 1) << 2;
    int brow = tid >> 5, bcol = (tid & 31) << 2;
    const float* Ap = A + (size_t)(bm + arow) * K + acol;
    const float* Bp = Bm + (size_t)brow * N + bn + bcol;
    int ty = (tid >> 4) << 3, tx = (tid & 15) << 3;

    float acc[8][8];
#pragma unroll
    for (int i = 0; i < 8; i++)
#pragma unroll
        for (int j = 0; j < 8; j++) acc[i][j] = 0.f;

    for (int k0 = 0; k0 < K; k0 += 8) {
        float4 av = *(const float4*)Ap;
        float4 bv = *(const float4*)Bp;
        As[acol + 0][arow] = av.x;
        As[acol + 1][arow] = av.y;
        As[acol + 2][arow] = av.z;
        As[acol + 3][arow] = av.w;
        *(float4*)&Bs[brow][bcol] = bv;
        __syncthreads();
#pragma unroll
        for (int k = 0; k < 8; k++) {
            float a[8], bb[8];
            *(float4*)&a[0]  = *(const float4*)&As[k][ty];
            *(float4*)&a[4]  = *(const float4*)&As[k][ty + 4];
            *(float4*)&bb[0] = *(const float4*)&Bs[k][tx];
            *(float4*)&bb[4] = *(const float4*)&Bs[k][tx + 4];
#pragma unroll
            for (int i = 0; i < 8; i++)
#pragma unroll
                for (int j = 0; j < 8; j++)
                    acc[i][j] += a[i] * bb[j];
        }
        __syncthreads();
        Ap += 8;
        Bp += (size_t)8 * N;
    }

#pragma unroll
    for (int i = 0; i < 8; i++) {
        int gm = bm + ty + i;
#pragma unroll
        for (int j = 0; j < 8; j++) {
            int gn = bn + tx + j;
            float v = acc[i][j] + bias[gn];
            if (EPI == 1) v = v * normcdff(v);   // exact GELU: v * Phi(v)
            if (EPI == 2) v += R[(size_t)gm * N + gn];
            C[(size_t)gm * N + gn] = v;
        }
    }
}

// ---------------- RoPE via precomputed tables, applied to Q and K in place ----------------
__global__ void rope_kernel(float* __restrict__ Q, float* __restrict__ K,
                            const float* __restrict__ ct, const float* __restrict__ st) {
    int idx = blockIdx.x * blockDim.x + threadIdx.x;   // BT * (DD/2)
    if (idx >= BT * (DD / 2)) return;
    int r  = idx / (DD / 2);
    int c2 = idx % (DD / 2);
    int p  = c2 & 31;            // pair index within head
    int t  = r & (TT - 1);
    float c = ct[t * 32 + p];
    float s = st[t * 32 + p];
    size_t base = (size_t)r * DD + ((size_t)c2 << 1);
    float q0 = Q[base], q1 = Q[base + 1];
    Q[base]     = q0 * c - q1 * s;
    Q[base + 1] = q0 * s + q1 * c;
    float k0 = K[base], k1 = K[base + 1];
    K[base]     = k0 * c - k1 * s;
    K[base + 1] = k0 * s + k1 * c;
}

// ---------------- scores: 4 q-rows per block, S[bh,q,k] = (Q[q]·K[k])/8, k <= q only -------
__global__ __launch_bounds__(256)
void scores4_kernel(const float* __restrict__ Q, const float* __restrict__ K,
                    float* __restrict__ S) {
    int q0 = blockIdx.x << 2;       // first of 4 query rows
    int bh = blockIdx.y;
    int b = bh >> 4, h = bh & 15;
    __shared__ float sq[4][64];
    int tid = threadIdx.x;
    {
        int qi = tid >> 6, d = tid & 63;
        sq[qi][d] = Q[((size_t)b * TT + q0 + qi) * DD + h * 64 + d];
    }
    __syncthreads();
    const float* Kb = K + (size_t)b * TT * DD + h * 64;
    float* Sb = S + (size_t)bh * TT * TT;
    int kmax = q0 + 4;              // exclusive bound: covers max nv of the 4 rows
    for (int k = tid; k < kmax; k += 256) {
        const float* Kr = Kb + (size_t)k * DD;
        float a0 = 0.f, a1 = 0.f, a2 = 0.f, a3 = 0.f;
#pragma unroll
        for (int d = 0; d < 64; d += 4) {
            float4 kv = *(const float4*)&Kr[d];
            a0 += sq[0][d] * kv.x + sq[0][d+1] * kv.y + sq[0][d+2] * kv.z + sq[0][d+3] * kv.w;
            a1 += sq[1][d] * kv.x + sq[1][d+1] * kv.y + sq[1][d+2] * kv.z + sq[1][d+3] * kv.w;
            a2 += sq[2][d] * kv.x + sq[2][d+1] * kv.y + sq[2][d+2] * kv.z + sq[2][d+3] * kv.w;
            a3 += sq[3][d] * kv.x + sq[3][d+1] * kv.y + sq[3][d+2] * kv.z + sq[3][d+3] * kv.w;
        }
        if (k <= q0 + 0) Sb[(size_t)(q0 + 0) * TT + k] = a0 * 0.125f;
        if (k <= q0 + 1) Sb[(size_t)(q0 + 1) * TT + k] = a1 * 0.125f;
        if (k <= q0 + 2) Sb[(size_t)(q0 + 2) * TT + k] = a2 * 0.125f;
        if (k <= q0 + 3) Sb[(size_t)(q0 + 3) * TT + k] = a3 * 0.125f;
    }
}

// ---------------- causal softmax per row over k in [0, q] ----------------
__global__ void softmax_kernel(float* __restrict__ S) {
    int q = blockIdx.x, bh = blockIdx.y;
    float* row = S + ((size_t)bh * TT + q) * TT;
    int nv = q + 1;
    int tid = threadIdx.x;

    __shared__ float red[8];

    float mx = -1e30f;
    for (int k = tid; k < nv; k += 256) mx = fmaxf(mx, row[k]);
#pragma unroll
    for (int o = 16; o > 0; o >>= 1) mx = fmaxf(mx, __shfl_xor_sync(0xffffffffu, mx, o));
    if ((tid & 31) == 0) red[tid >> 5] = mx;
    __syncthreads();
    if (tid == 0) {
        float m = red[0];
#pragma unroll
        for (int i = 1; i < 8; i++) m = fmaxf(m, red[i]);
        red[0] = m;
    }
    __syncthreads();
    float gmx = red[0];
    __syncthreads();

    float e[8];
    float sum = 0.f;
    int it = 0;
    for (int k = tid; k < nv; k += 256) {
        float ev = expf(row[k] - gmx);
        e[it++] = ev;
        sum += ev;
    }
#pragma unroll
    for (int o = 16; o > 0; o >>= 1) sum += __shfl_xor_sync(0xffffffffu, sum, o);
    if ((tid & 31) == 0) red[tid >> 5] = sum;
    __syncthreads();
    if (tid == 0) {
        float t = 0.f;
#pragma unroll
        for (int i = 0; i < 8; i++) t += red[i];
        red[0] = t;
    }
    __syncthreads();
    float invs = 1.f / red[0];

    it = 0;
    for (int k = tid; k < nv; k += 256)
        row[k] = e[it++] * invs;
}

// ---------------- PV: 4 q-rows per block; O[q,d] = sum_{k<=q} P[q,k] V[k,d] ----------------
__global__ __launch_bounds__(256)
void pv4_kernel(const float* __restrict__ S, const float* __restrict__ V,
                float* __restrict__ O) {
    int q0 = blockIdx.x << 2;
    int bh = blockIdx.y;
    int b = bh >> 4, h = bh & 15;
    int tid = threadIdx.x;
    int qi = tid >> 6;           // 0..3
    int d  = tid & 63;           // 0..63
    int q  = q0 + qi;
    const float* row = S + ((size_t)bh * TT + q) * TT;
    const float* Vb  = V + (size_t)b * TT * DD + h * 64 + d;
    float acc = 0.f;
    int nv = q + 1;
#pragma unroll 4
    for (int k = 0; k < nv; k++)
        acc += row[k] * Vb[(size_t)k * DD];
    O[((size_t)b * TT + q) * DD + h * 64 + d] = acc;
}

// ---------------- launch sequence ----------------
extern "C" void kernel_launch(void* const* d_in, const int* in_sizes, int n_in,
                              void* d_out, int out_size) {
    const int*   actions = (const int*)d_in[0];
    const int*   observ  = (const int*)d_in[1];
    const float* aemb    = (const float*)d_in[2];
    const float* oemb    = (const float*)d_in[3];
    const float* temb    = (const float*)d_in[4];
    const float* Wq      = (const float*)d_in[5];
    const float* bq      = (const float*)d_in[6];
    const float* Wk      = (const float*)d_in[7];
    const float* bk      = (const float*)d_in[8];
    const float* Wv      = (const float*)d_in[9];
    const float* bv      = (const float*)d_in[10];
    const float* Wo      = (const float*)d_in[11];
    const float* bo      = (const float*)d_in[12];
    const float* ln1_g   = (const float*)d_in[13];
    const float* ln1_b   = (const float*)d_in[14];
    const float* ln2_g   = (const float*)d_in[15];
    const float* ln2_b   = (const float*)d_in[16];
    const float* W1      = (const float*)d_in[17];
    const float* b1      = (const float*)d_in[18];
    const float* W2      = (const float*)d_in[19];
    const float* b2      = (const float*)d_in[20];
    const float* out_g   = (const float*)d_in[21];
    const float* out_b   = (const float*)d_in[22];
    const float* Wout    = (const float*)d_in[23];
    const float* bout    = (const float*)d_in[24];

    float *x, *h, *q, *k, *v, *o, *ff, *S, *ct, *st;
    cudaGetSymbolAddress((void**)&x,  g_x);
    cudaGetSymbolAddress((void**)&h,  g_h);
    cudaGetSymbolAddress((void**)&q,  g_q);
    cudaGetSymbolAddress((void**)&k,  g_k);
    cudaGetSymbolAddress((void**)&v,  g_v);
    cudaGetSymbolAddress((void**)&o,  g_o);
    cudaGetSymbolAddress((void**)&ff, g_ff);
    cudaGetSymbolAddress((void**)&S,  g_S);
    cudaGetSymbolAddress((void**)&ct, g_cos);
    cudaGetSymbolAddress((void**)&st, g_sin);

    trig_kernel<<<(TT * 32 + 255) / 256, 256>>>(ct, st);
    embed_kernel<<<(BT * DD + 255) / 256, 256>>>(actions, observ, aemb, oemb, temb, x);

    for (int i = 0; i < LL; i++) {
        ln_kernel<<<BT, 256>>>(x, ln1_g + (size_t)i * DD, ln1_b + (size_t)i * DD, h);

        sgemm_kernel<0><<<dim3(DD / 128, BT / 128), 256>>>(
            h, Wq + (size_t)i * DD * DD, bq + (size_t)i * DD, nullptr, q, BT, DD, DD);
        sgemm_kernel<0><<<dim3(DD / 128, BT / 128), 256>>>(
            h, Wk + (size_t)i * DD * DD, bk + (size_t)i * DD, nullptr, k, BT, DD, DD);
        sgemm_kernel<0><<<dim3(DD / 128, BT / 128), 256>>>(
            h, Wv + (size_t)i * DD * DD, bv + (size_t)i * DD, nullptr, v, BT, DD, DD);

        rope_kernel<<<(BT * (DD / 2) + 255) / 256, 256>>>(q, k, ct, st);

        scores4_kernel<<<dim3(TT / 4, BB * HH), 256>>>(q, k, S);
        softmax_kernel<<<dim3(TT, BB * HH), 256>>>(S);
        pv4_kernel<<<dim3(TT / 4, BB * HH), 256>>>(S, v, o);

        sgemm_kernel<2><<<dim3(DD / 128, BT / 128), 256>>>(
            o, Wo + (size_t)i * DD * DD, bo + (size_t)i * DD, x, x, BT, DD, DD);

        ln_kernel<<<BT, 256>>>(x, ln2_g + (size_t)i * DD, ln2_b + (size_t)i * DD, h);

        sgemm_kernel<1><<<dim3(DFF / 128, BT / 128), 256>>>(
            h, W1 + (size_t)i * DD * DFF, b1 + (size_t)i * DFF, nullptr, ff, BT, DFF, DD);
        sgemm_kernel<2><<<dim3(DD / 128, BT / 128), 256>>>(
            ff, W2 + (size_t)i * DFF * DD, b2 + (size_t)i * DD, x, x, BT, DD, DFF);
    }

    ln_kernel<<<BT, 256>>>(x, out_g, out_b, h);
    sgemm_kernel<0><<<dim3(OV / 128, BT / 128), 256>>>(
        h, Wout, bout, nullptr, (float*)d_out, BT, OV, DD);
}

// round 5
// speedup vs baseline: 1.4942x; 1.4942x over previous
#include <cuda_runtime.h>
#include <math.h>

#define LL 2
#define DD 1024
#define HH 16
#define DHH 64
#define DFF 4096
#define BB 2
#define TT 2048
#define OV 4096
#define BT (BB*TT)   // 4096

// ---------------- scratch (device globals; no runtime allocation) ----------------
__device__ float g_x [BT*DD];
__device__ float g_h [BT*DD];
__device__ float g_q [BT*DD];
__device__ float g_k [BT*DD];
__device__ float g_v [BT*DD];
__device__ float g_o [BT*DD];
__device__ float g_ff[BT*DFF];
__device__ float g_S [(size_t)BB*HH*TT*TT];   // 512 MB score / prob scratch
__device__ float g_cos[TT*32];
__device__ float g_sin[TT*32];

// ---------------- packed f32x2 helpers (ptxas will not auto-emit FFMA2) ----------------
__device__ __forceinline__ unsigned long long pack2(float x) {
    unsigned long long r;
    asm("mov.b64 %0, {%1, %1};" : "=l"(r) : "f"(x));
    return r;
}
__device__ __forceinline__ void fma2(unsigned long long& acc, unsigned long long a,
                                     unsigned long long b) {
    asm("fma.rn.f32x2 %0, %1, %2, %0;" : "+l"(acc) : "l"(a), "l"(b));
}
__device__ __forceinline__ void unpack2(unsigned long long v, float& lo, float& hi) {
    asm("mov.b64 {%0, %1}, %2;" : "=f"(lo), "=f"(hi) : "l"(v));
}

// ---------------- RoPE trig tables (double precision; fast-math-proof) ----------------
__global__ void trig_kernel(float* __restrict__ ct, float* __restrict__ st) {
    int i = blockIdx.x * 256 + threadIdx.x;
    if (i >= TT * 32) return;
    int t = i >> 5, p = i & 31;
    double inv = exp2(-13.287712379549449 * ((double)(2 * p) * (1.0 / 64.0)));
    float invf = (float)inv;
    float angf = (float)((double)t * (double)invf);   // == fp32 multiply rounding
    double c, s;
    sincos((double)angf, &s, &c);                     // exact trig of the fp32 angle
    ct[i] = (float)c;
    st[i] = (float)s;
}

// ---------------- embedding ----------------
__global__ void embed_kernel(const int* __restrict__ act, const int* __restrict__ obs,
                             const float* __restrict__ aemb, const float* __restrict__ oemb,
                             const float* __restrict__ temb, float* __restrict__ x) {
    int idx = blockIdx.x * blockDim.x + threadIdx.x;
    if (idx >= BT * DD) return;
    int r = idx / DD, d = idx % DD;
    x[idx] = aemb[(size_t)act[r] * DD + d] + temb[d]
           + oemb[(size_t)obs[r] * DD + d] + temb[DD + d];
}

// ---------------- layernorm (one block per row, 256 threads) ----------------
__global__ void ln_kernel(const float* __restrict__ x, const float* __restrict__ g,
                          const float* __restrict__ b, float* __restrict__ y) {
    int r = blockIdx.x;
    const float* xr = x + (size_t)r * DD;
    float v[4];
    float s = 0.f, ss = 0.f;
#pragma unroll
    for (int i = 0; i < 4; i++) {
        float t = xr[threadIdx.x + i * 256];
        v[i] = t; s += t; ss += t * t;
    }
#pragma unroll
    for (int o = 16; o > 0; o >>= 1) {
        s  += __shfl_xor_sync(0xffffffffu, s,  o);
        ss += __shfl_xor_sync(0xffffffffu, ss, o);
    }
    __shared__ float rs[8], rss[8];
    int w = threadIdx.x >> 5;
    if ((threadIdx.x & 31) == 0) { rs[w] = s; rss[w] = ss; }
    __syncthreads();
    if (threadIdx.x == 0) {
        float a = 0.f, c = 0.f;
#pragma unroll
        for (int i = 0; i < 8; i++) { a += rs[i]; c += rss[i]; }
        rs[0] = a; rss[0] = c;
    }
    __syncthreads();
    float mean = rs[0] * (1.f / DD);
    float var  = rss[0] * (1.f / DD) - mean * mean;
    float inv  = rsqrtf(var + 1e-5f);
    float* yr = y + (size_t)r * DD;
#pragma unroll
    for (int i = 0; i < 4; i++) {
        int d = threadIdx.x + i * 256;
        yr[d] = (v[i] - mean) * inv * g[d] + b[d];
    }
}

// ---------------- SGEMM with packed f32x2 FMAs ----------------
// EPI: 0 = bias only, 1 = bias + exact GELU, 2 = bias + residual add
template <int EPI>
__global__ __launch_bounds__(256, 2)
void sgemm_kernel(const float* __restrict__ A, const float* __restrict__ Bm,
                  const float* __restrict__ bias, const float* __restrict__ R,
                  float* __restrict__ C, int M, int N, int K) {
    __shared__ float As[8][128];
    __shared__ float Bs[8][128];
    int tid = threadIdx.x;
    int bm = blockIdx.y << 7, bn = blockIdx.x << 7;
    int arow = tid >> 1, acol = (tid & 1) << 2;
    int brow = tid >> 5, bcol = (tid & 31) << 2;
    const float* Ap = A + (size_t)(bm + arow) * K + acol;
    const float* Bp = Bm + (size_t)brow * N + bn + bcol;
    int ty = (tid >> 4) << 3, tx = (tid & 15) << 3;

    unsigned long long acc2[8][4];
#pragma unroll
    for (int i = 0; i < 8; i++)
#pragma unroll
        for (int j = 0; j < 4; j++) acc2[i][j] = 0ull;

    for (int k0 = 0; k0 < K; k0 += 8) {
        float4 av = *(const float4*)Ap;
        float4 bv = *(const float4*)Bp;
        As[acol + 0][arow] = av.x;
        As[acol + 1][arow] = av.y;
        As[acol + 2][arow] = av.z;
        As[acol + 3][arow] = av.w;
        *(float4*)&Bs[brow][bcol] = bv;
        __syncthreads();
#pragma unroll
        for (int k = 0; k < 8; k++) {
            float a[8];
            *(float4*)&a[0] = *(const float4*)&As[k][ty];
            *(float4*)&a[4] = *(const float4*)&As[k][ty + 4];
            unsigned long long b2[4];
            *(ulonglong2*)&b2[0] = *(const ulonglong2*)&Bs[k][tx];
            *(ulonglong2*)&b2[2] = *(const ulonglong2*)&Bs[k][tx + 4];
            unsigned long long a2[8];
#pragma unroll
            for (int i = 0; i < 8; i++) a2[i] = pack2(a[i]);
#pragma unroll
            for (int i = 0; i < 8; i++)
#pragma unroll
                for (int j = 0; j < 4; j++)
                    fma2(acc2[i][j], a2[i], b2[j]);
        }
        __syncthreads();
        Ap += 8;
        Bp += (size_t)8 * N;
    }

#pragma unroll
    for (int i = 0; i < 8; i++) {
        int gm = bm + ty + i;
#pragma unroll
        for (int j = 0; j < 4; j++) {
            float v0, v1;
            unpack2(acc2[i][j], v0, v1);
            int gn = bn + tx + 2 * j;
            v0 += bias[gn];
            v1 += bias[gn + 1];
            if (EPI == 1) { v0 = v0 * normcdff(v0); v1 = v1 * normcdff(v1); }
            if (EPI == 2) {
                v0 += R[(size_t)gm * N + gn];
                v1 += R[(size_t)gm * N + gn + 1];
            }
            C[(size_t)gm * N + gn]     = v0;
            C[(size_t)gm * N + gn + 1] = v1;
        }
    }
}

// ---------------- RoPE via precomputed tables, applied to Q and K in place ----------------
__global__ void rope_kernel(float* __restrict__ Q, float* __restrict__ K,
                            const float* __restrict__ ct, const float* __restrict__ st) {
    int idx = blockIdx.x * blockDim.x + threadIdx.x;   // BT * (DD/2)
    if (idx >= BT * (DD / 2)) return;
    int r  = idx / (DD / 2);
    int c2 = idx % (DD / 2);
    int p  = c2 & 31;            // pair index within head
    int t  = r & (TT - 1);
    float c = ct[t * 32 + p];
    float s = st[t * 32 + p];
    size_t base = (size_t)r * DD + ((size_t)c2 << 1);
    float q0 = Q[base], q1 = Q[base + 1];
    Q[base]     = q0 * c - q1 * s;
    Q[base + 1] = q0 * s + q1 * c;
    float k0 = K[base], k1 = K[base + 1];
    K[base]     = k0 * c - k1 * s;
    K[base + 1] = k0 * s + k1 * c;
}

// ---------------- attention scores: 64x64 tiles, k-tile <= q-tile ----------------
__global__ __launch_bounds__(256)
void attn_scores_kernel(const float* __restrict__ Q, const float* __restrict__ K,
                        float* __restrict__ S) {
    int qt = blockIdx.x, kt = blockIdx.y, bh = blockIdx.z;
    if (kt > qt) return;                      // fully masked tile
    int b = bh >> 4, h = bh & 15;
    const float* Qb = Q + ((size_t)b * TT + (size_t)qt * 64) * DD + h * 64;
    const float* Kb = K + ((size_t)b * TT + (size_t)kt * 64) * DD + h * 64;

    __shared__ float sQ[64][65];
    __shared__ float sK[64][65];
    int tid = threadIdx.x;
    int lr = tid >> 4;
    int lc = (tid & 15) << 2;
#pragma unroll
    for (int i = 0; i < 4; i++) {
        int row = lr + i * 16;
        float4 qv = *(const float4*)&Qb[(size_t)row * DD + lc];
        sQ[row][lc] = qv.x; sQ[row][lc + 1] = qv.y; sQ[row][lc + 2] = qv.z; sQ[row][lc + 3] = qv.w;
        float4 kv = *(const float4*)&Kb[(size_t)row * DD + lc];
        sK[row][lc] = kv.x; sK[row][lc + 1] = kv.y; sK[row][lc + 2] = kv.z; sK[row][lc + 3] = kv.w;
    }
    __syncthreads();

    int ty = (tid >> 4) << 2, tx = (tid & 15) << 2;
    float acc[4][4] = {};
#pragma unroll 8
    for (int d = 0; d < 64; d++) {
        float qv[4], kv[4];
#pragma unroll
        for (int j = 0; j < 4; j++) { qv[j] = sQ[ty + j][d]; kv[j] = sK[tx + j][d]; }
#pragma unroll
        for (int i = 0; i < 4; i++)
#pragma unroll
            for (int j = 0; j < 4; j++)
                acc[i][j] += qv[i] * kv[j];
    }
    float* Sp = S + ((size_t)bh * TT + (size_t)qt * 64) * TT + (size_t)kt * 64;
#pragma unroll
    for (int i = 0; i < 4; i++)
#pragma unroll
        for (int j = 0; j < 4; j++)
            Sp[(size_t)(ty + i) * TT + tx + j] = acc[i][j] * 0.125f;
}

// ---------------- causal softmax per row; zero-fills (q, tile-boundary) ----------------
__global__ void softmax_kernel(float* __restrict__ S) {
    int q = blockIdx.x, bh = blockIdx.y;
    float* row = S + ((size_t)bh * TT + q) * TT;
    int nv = q + 1;
    int kend = (q & ~63) + 64;   // diagonal-tile boundary (PV reads up to here)
    int tid = threadIdx.x;

    __shared__ float red[8];

    float mx = -1e30f;
    for (int k = tid; k < nv; k += 256) mx = fmaxf(mx, row[k]);
#pragma unroll
    for (int o = 16; o > 0; o >>= 1) mx = fmaxf(mx, __shfl_xor_sync(0xffffffffu, mx, o));
    if ((tid & 31) == 0) red[tid >> 5] = mx;
    __syncthreads();
    if (tid == 0) {
        float m = red[0];
#pragma unroll
        for (int i = 1; i < 8; i++) m = fmaxf(m, red[i]);
        red[0] = m;
    }
    __syncthreads();
    float gmx = red[0];
    __syncthreads();

    float e[8];
    float sum = 0.f;
    int it = 0;
    for (int k = tid; k < nv; k += 256) {
        float ev = expf(row[k] - gmx);
        e[it++] = ev;
        sum += ev;
    }
#pragma unroll
    for (int o = 16; o > 0; o >>= 1) sum += __shfl_xor_sync(0xffffffffu, sum, o);
    if ((tid & 31) == 0) red[tid >> 5] = sum;
    __syncthreads();
    if (tid == 0) {
        float t = 0.f;
#pragma unroll
        for (int i = 0; i < 8; i++) t += red[i];
        red[0] = t;
    }
    __syncthreads();
    float invs = 1.f / red[0];

    it = 0;
    for (int k = tid; k < nv; k += 256)
        row[k] = e[it++] * invs;
    for (int k = nv + tid; k < kend; k += 256)
        row[k] = 0.f;            // masked tail of the diagonal tile
}

// ---------------- PV: 64q x 64d tiles; O[q,:] = sum_{kt<=qt} P-tile @ V-tile ----------------
__global__ __launch_bounds__(256)
void attn_pv_kernel(const float* __restrict__ S, const float* __restrict__ V,
                    float* __restrict__ O) {
    int qt = blockIdx.x, bh = blockIdx.y;
    int b = bh >> 4, h = bh & 15;
    __shared__ float sP[64][65];
    __shared__ float sV[64][68];
    int tid = threadIdx.x;
    int lr = tid >> 4;
    int lc = (tid & 15) << 2;
    int ty = (tid >> 4) << 2, tx = (tid & 15) << 2;
    float acc[4][4] = {};

    const float* Srow = S + ((size_t)bh * TT + (size_t)qt * 64) * TT;
    const float* Vb = V + (size_t)b * TT * DD + h * 64;

    for (int kt = 0; kt <= qt; kt++) {
#pragma unroll
        for (int i = 0; i < 4; i++) {
            int row = lr + i * 16;
            float4 pv = *(const float4*)&Srow[(size_t)row * TT + (size_t)kt * 64 + lc];
            sP[row][lc] = pv.x; sP[row][lc + 1] = pv.y; sP[row][lc + 2] = pv.z; sP[row][lc + 3] = pv.w;
            float4 vv = *(const float4*)&Vb[(size_t)(kt * 64 + row) * DD + lc];
            *(float4*)&sV[row][lc] = vv;
        }
        __syncthreads();
#pragma unroll 8
        for (int kk = 0; kk < 64; kk++) {
            float p[4];
            float vv[4];
            *(float4*)vv = *(const float4*)&sV[kk][tx];
#pragma unroll
            for (int j = 0; j < 4; j++) p[j] = sP[ty + j][kk];
#pragma unroll
            for (int i = 0; i < 4; i++)
#pragma unroll
                for (int j = 0; j < 4; j++)
                    acc[i][j] += p[i] * vv[j];
        }
        __syncthreads();
    }

    float* Ob = O + ((size_t)b * TT + (size_t)qt * 64) * DD + h * 64;
#pragma unroll
    for (int i = 0; i < 4; i++)
#pragma unroll
        for (int j = 0; j < 4; j++)
            Ob[(size_t)(ty + i) * DD + tx + j] = acc[i][j];
}

// ---------------- launch sequence ----------------
extern "C" void kernel_launch(void* const* d_in, const int* in_sizes, int n_in,
                              void* d_out, int out_size) {
    const int*   actions = (const int*)d_in[0];
    const int*   observ  = (const int*)d_in[1];
    const float* aemb    = (const float*)d_in[2];
    const float* oemb    = (const float*)d_in[3];
    const float* temb    = (const float*)d_in[4];
    const float* Wq      = (const float*)d_in[5];
    const float* bq      = (const float*)d_in[6];
    const float* Wk      = (const float*)d_in[7];
    const float* bk      = (const float*)d_in[8];
    const float* Wv      = (const float*)d_in[9];
    const float* bv      = (const float*)d_in[10];
    const float* Wo      = (const float*)d_in[11];
    const float* bo      = (const float*)d_in[12];
    const float* ln1_g   = (const float*)d_in[13];
    const float* ln1_b   = (const float*)d_in[14];
    const float* ln2_g   = (const float*)d_in[15];
    const float* ln2_b   = (const float*)d_in[16];
    const float* W1      = (const float*)d_in[17];
    const float* b1      = (const float*)d_in[18];
    const float* W2      = (const float*)d_in[19];
    const float* b2      = (const float*)d_in[20];
    const float* out_g   = (const float*)d_in[21];
    const float* out_b   = (const float*)d_in[22];
    const float* Wout    = (const float*)d_in[23];
    const float* bout    = (const float*)d_in[24];

    float *x, *h, *q, *k, *v, *o, *ff, *S, *ct, *st;
    cudaGetSymbolAddress((void**)&x,  g_x);
    cudaGetSymbolAddress((void**)&h,  g_h);
    cudaGetSymbolAddress((void**)&q,  g_q);
    cudaGetSymbolAddress((void**)&k,  g_k);
    cudaGetSymbolAddress((void**)&v,  g_v);
    cudaGetSymbolAddress((void**)&o,  g_o);
    cudaGetSymbolAddress((void**)&ff, g_ff);
    cudaGetSymbolAddress((void**)&S,  g_S);
    cudaGetSymbolAddress((void**)&ct, g_cos);
    cudaGetSymbolAddress((void**)&st, g_sin);

    trig_kernel<<<(TT * 32 + 255) / 256, 256>>>(ct, st);
    embed_kernel<<<(BT * DD + 255) / 256, 256>>>(actions, observ, aemb, oemb, temb, x);

    for (int i = 0; i < LL; i++) {
        ln_kernel<<<BT, 256>>>(x, ln1_g + (size_t)i * DD, ln1_b + (size_t)i * DD, h);

        sgemm_kernel<0><<<dim3(DD / 128, BT / 128), 256>>>(
            h, Wq + (size_t)i * DD * DD, bq + (size_t)i * DD, nullptr, q, BT, DD, DD);
        sgemm_kernel<0><<<dim3(DD / 128, BT / 128), 256>>>(
            h, Wk + (size_t)i * DD * DD, bk + (size_t)i * DD, nullptr, k, BT, DD, DD);
        sgemm_kernel<0><<<dim3(DD / 128, BT / 128), 256>>>(
            h, Wv + (size_t)i * DD * DD, bv + (size_t)i * DD, nullptr, v, BT, DD, DD);

        rope_kernel<<<(BT * (DD / 2) + 255) / 256, 256>>>(q, k, ct, st);

        attn_scores_kernel<<<dim3(TT / 64, TT / 64, BB * HH), 256>>>(q, k, S);
        softmax_kernel<<<dim3(TT, BB * HH), 256>>>(S);
        attn_pv_kernel<<<dim3(TT / 64, BB * HH), 256>>>(S, v, o);

        sgemm_kernel<2><<<dim3(DD / 128, BT / 128), 256>>>(
            o, Wo + (size_t)i * DD * DD, bo + (size_t)i * DD, x, x, BT, DD, DD);

        ln_kernel<<<BT, 256>>>(x, ln2_g + (size_t)i * DD, ln2_b + (size_t)i * DD, h);

        sgemm_kernel<1><<<dim3(DFF / 128, BT / 128), 256>>>(
            h, W1 + (size_t)i * DD * DFF, b1 + (size_t)i * DFF, nullptr, ff, BT, DFF, DD);
        sgemm_kernel<2><<<dim3(DD / 128, BT / 128), 256>>>(
            ff, W2 + (size_t)i * DFF * DD, b2 + (size_t)i * DD, x, x, BT, DD, DFF);
    }

    ln_kernel<<<BT, 256>>>(x, out_g, out_b, h);
    sgemm_kernel<0><<<dim3(OV / 128, BT / 128), 256>>>(
        h, Wout, bout, nullptr, (float*)d_out, BT, OV, DD);
}

// round 7
// speedup vs baseline: 2.5539x; 1.7092x over previous
#include <cuda_runtime.h>
#include <cuda_bf16.h>
#include <math.h>
#include <stdint.h>

#define LL 2
#define DD 1024
#define HH 16
#define DHH 64
#define DFF 4096
#define BB 2
#define TT 2048
#define OV 4096
#define BT (BB*TT)   // 4096

// ---------------- scratch (device globals; no runtime allocation) ----------------
__device__ float g_x [BT*DD];
__device__ float g_h [BT*DD];
__device__ float g_q [BT*DD];
__device__ float g_k [BT*DD];
__device__ float g_v [BT*DD];
__device__ float g_o [BT*DD];
__device__ float g_ff[BT*DFF];
__device__ float g_S [(size_t)BB*HH*TT*TT];   // 512 MB score / prob scratch
__device__ float g_cos[TT*32];
__device__ float g_sin[TT*32];
// bf16 split operands (16B-aligned for uint4 access)
__device__ __align__(16) __nv_bfloat16 g_ah[(size_t)BT*DFF];   // A hi
__device__ __align__(16) __nv_bfloat16 g_al[(size_t)BT*DFF];   // A lo
__device__ __align__(16) __nv_bfloat16 g_bh[(size_t)DFF*DD];   // B^T hi  [N,K]
__device__ __align__(16) __nv_bfloat16 g_bl[(size_t)DFF*DD];   // B^T lo

// ---------------- warp-MMA primitives (baseline PTX; no sm_103a features) ----------
__device__ __forceinline__ uint32_t smem_u32(const void* p) {
    uint32_t a;
    asm("{ .reg .u64 t; cvta.to.shared.u64 t, %1; cvt.u32.u64 %0, t; }" : "=r"(a) : "l"(p));
    return a;
}
__device__ __forceinline__ void ldm4(uint32_t* r, uint32_t addr) {
    asm volatile("ldmatrix.sync.aligned.m8n8.x4.shared.b16 {%0,%1,%2,%3}, [%4];"
                 : "=r"(r[0]), "=r"(r[1]), "=r"(r[2]), "=r"(r[3]) : "r"(addr));
}
__device__ __forceinline__ void mma16816(float* d, const uint32_t* a, const uint32_t* b) {
    asm volatile("mma.sync.aligned.m16n8k16.row.col.f32.bf16.bf16.f32 "
                 "{%0,%1,%2,%3}, {%4,%5,%6,%7}, {%8,%9}, {%0,%1,%2,%3};"
                 : "+f"(d[0]), "+f"(d[1]), "+f"(d[2]), "+f"(d[3])
                 : "r"(a[0]), "r"(a[1]), "r"(a[2]), "r"(a[3]), "r"(b[0]), "r"(b[1]));
}

// ---------------- split-precision conversion: A (row-major passthrough) ----------------
__global__ void convA_kernel(const float* __restrict__ X, __nv_bfloat16* __restrict__ hi,
                             __nv_bfloat16* __restrict__ lo, int n4) {
    int i = blockIdx.x * 256 + threadIdx.x;
    if (i >= n4) return;
    float4 v = ((const float4*)X)[i];
    __nv_bfloat16 h0 = __float2bfloat16_rn(v.x), h1 = __float2bfloat16_rn(v.y);
    __nv_bfloat16 h2 = __float2bfloat16_rn(v.z), h3 = __float2bfloat16_rn(v.w);
    __nv_bfloat162 H0; H0.x = h0; H0.y = h1;
    __nv_bfloat162 H1; H1.x = h2; H1.y = h3;
    __nv_bfloat162 L0, L1;
    L0.x = __float2bfloat16_rn(v.x - __bfloat162float(h0));
    L0.y = __float2bfloat16_rn(v.y - __bfloat162float(h1));
    L1.x = __float2bfloat16_rn(v.z - __bfloat162float(h2));
    L1.y = __float2bfloat16_rn(v.w - __bfloat162float(h3));
    ((__nv_bfloat162*)hi)[2*i]     = H0;
    ((__nv_bfloat162*)hi)[2*i + 1] = H1;
    ((__nv_bfloat162*)lo)[2*i]     = L0;
    ((__nv_bfloat162*)lo)[2*i + 1] = L1;
}

// ---------------- split + transpose: W[K,N] -> Bt[N,K] hi/lo ----------------
__global__ void convT_kernel(const float* __restrict__ W, __nv_bfloat16* __restrict__ ht,
                             __nv_bfloat16* __restrict__ lt, int K, int N) {
    __shared__ float t[64][33];
    int n0 = blockIdx.x * 32, k0 = blockIdx.y * 64;
    int tx = threadIdx.x & 31, ty = threadIdx.x >> 5;
#pragma unroll
    for (int ky = 0; ky < 64; ky += 8)
        t[ky + ty][tx] = W[(size_t)(k0 + ky + ty) * N + n0 + tx];
    __syncthreads();
    int kl = threadIdx.x & 63, nb = threadIdx.x >> 6;
#pragma unroll
    for (int n = nb; n < 32; n += 4) {
        float v = t[kl][n];
        __nv_bfloat16 h = __float2bfloat16_rn(v);
        size_t o = (size_t)(n0 + n) * K + k0 + kl;
        ht[o] = h;
        lt[o] = __float2bfloat16_rn(v - __bfloat162float(h));
    }
}

// ---------------- HMMA split-bf16 GEMM: C[M,N] = A@B + bias (+epi) ----------------
// A: (Ahi,Alo)[M,K] row-major; B: (Bhi,Blo)[N,K] row-major (= col-major [K,N]).
// 128x128 CTA tile, 8 warps (2x4), warp tile 64x32, K-chunk 64.
// smem: 4 tiles of 128 rows x 72 bf16 (144 B/row; 9 16B-units -> ldmatrix conflict-free)
#define TROW 72
#define TBYTES (128*TROW*2)   // 18432 per tile
#define GSMEM (4*TBYTES)      // 73728

// EPI: 0 = bias, 1 = bias + GELU, 2 = bias + residual
template <int EPI>
__global__ __launch_bounds__(256)
void gemm_mma(const __nv_bfloat16* __restrict__ Ahi, const __nv_bfloat16* __restrict__ Alo,
              const __nv_bfloat16* __restrict__ Bhi, const __nv_bfloat16* __restrict__ Blo,
              const float* __restrict__ bias, const float* __restrict__ R,
              float* __restrict__ C, int M, int N, int K) {
    extern __shared__ __align__(16) char smem[];
    const uint32_t sb = smem_u32(smem);
    int tid = threadIdx.x, lane = tid & 31, w = tid >> 5;
    int wm = w >> 2, wn = w & 3;
    int bm = blockIdx.y << 7, bn = blockIdx.x << 7;

    float acc[4][4][4];
#pragma unroll
    for (int i = 0; i < 4; i++)
#pragma unroll
        for (int j = 0; j < 4; j++)
#pragma unroll
            for (int z = 0; z < 4; z++) acc[i][j][z] = 0.f;

    // ldmatrix lane-invariant offsets (bytes)
    int a_row = wm * 64 + (lane & 15);
    int a_col = (lane >> 4) << 3;
    uint32_t aoff_h = sb + (uint32_t)(a_row * TROW + a_col) * 2;
    uint32_t aoff_l = aoff_h + TBYTES;
    int b_row = wn * 32 + ((lane >> 4) << 3) + (lane & 7);
    int b_col = ((lane >> 3) & 1) << 3;
    uint32_t boff_h = sb + 2 * TBYTES + (uint32_t)(b_row * TROW + b_col) * 2;
    uint32_t boff_l = boff_h + TBYTES;

    int lrow = tid >> 3, lseg = tid & 7;   // 32 rows x 8 16B-segs per pass

    for (int kb = 0; kb < K; kb += 64) {
        __syncthreads();
#pragma unroll
        for (int i = 0; i < 4; i++) {
            int row = lrow + i * 32;
            uint32_t so = (uint32_t)(row * TROW * 2 + lseg * 16);
            size_t ga = (size_t)(bm + row) * K + kb + lseg * 8;
            size_t gb = (size_t)(bn + row) * K + kb + lseg * 8;
            *(uint4*)(smem + so)              = *(const uint4*)(Ahi + ga);
            *(uint4*)(smem + so + TBYTES)     = *(const uint4*)(Alo + ga);
            *(uint4*)(smem + so + 2*TBYTES)   = *(const uint4*)(Bhi + gb);
            *(uint4*)(smem + so + 3*TBYTES)   = *(const uint4*)(Blo + gb);
        }
        __syncthreads();

#pragma unroll
        for (int ks = 0; ks < 4; ks++) {
            uint32_t ah[4][4], al[4][4], bh[8], bl[8];
            uint32_t kso = (uint32_t)(ks * 16 * 2);
#pragma unroll
            for (int mi = 0; mi < 4; mi++) {
                ldm4(ah[mi], aoff_h + (uint32_t)(mi * 16 * TROW * 2) + kso);
                ldm4(al[mi], aoff_l + (uint32_t)(mi * 16 * TROW * 2) + kso);
            }
            ldm4(&bh[0], boff_h + kso);
            ldm4(&bh[4], boff_h + (uint32_t)(16 * TROW * 2) + kso);
#pragma unroll
            for (int mi = 0; mi < 4; mi++)
#pragma unroll
                for (int ni = 0; ni < 4; ni++)
                    mma16816(acc[mi][ni], ah[mi], &bh[ni * 2]);
#pragma unroll
            for (int mi = 0; mi < 4; mi++)
#pragma unroll
                for (int ni = 0; ni < 4; ni++)
                    mma16816(acc[mi][ni], al[mi], &bh[ni * 2]);
            ldm4(&bl[0], boff_l + kso);
            ldm4(&bl[4], boff_l + (uint32_t)(16 * TROW * 2) + kso);
#pragma unroll
            for (int mi = 0; mi < 4; mi++)
#pragma unroll
                for (int ni = 0; ni < 4; ni++)
                    mma16816(acc[mi][ni], ah[mi], &bl[ni * 2]);
        }
    }

    // ---- epilogue: direct to global ----
#pragma unroll
    for (int mi = 0; mi < 4; mi++) {
#pragma unroll
        for (int ni = 0; ni < 4; ni++) {
            int r0 = bm + wm * 64 + mi * 16 + (lane >> 2);
            int c0 = bn + wn * 32 + ni * 8 + ((lane & 3) << 1);
#pragma unroll
            for (int half = 0; half < 2; half++) {
                int gm = r0 + half * 8;
                float v0 = acc[mi][ni][half * 2]     + bias[c0];
                float v1 = acc[mi][ni][half * 2 + 1] + bias[c0 + 1];
                if (EPI == 1) { v0 *= normcdff(v0); v1 *= normcdff(v1); }
                if (EPI == 2) {
                    v0 += R[(size_t)gm * N + c0];
                    v1 += R[(size_t)gm * N + c0 + 1];
                }
                float2 o; o.x = v0; o.y = v1;
                *(float2*)&C[(size_t)gm * N + c0] = o;
            }
        }
    }
}

// ---------------- RoPE trig tables (double precision; fast-math-proof) ----------------
__global__ void trig_kernel(float* __restrict__ ct, float* __restrict__ st) {
    int i = blockIdx.x * 256 + threadIdx.x;
    if (i >= TT * 32) return;
    int t = i >> 5, p = i & 31;
    double inv = exp2(-13.287712379549449 * ((double)(2 * p) * (1.0 / 64.0)));
    float invf = (float)inv;
    float angf = (float)((double)t * (double)invf);
    double c, s;
    sincos((double)angf, &s, &c);
    ct[i] = (float)c;
    st[i] = (float)s;
}

// ---------------- embedding ----------------
__global__ void embed_kernel(const int* __restrict__ act, const int* __restrict__ obs,
                             const float* __restrict__ aemb, const float* __restrict__ oemb,
                             const float* __restrict__ temb, float* __restrict__ x) {
    int idx = blockIdx.x * blockDim.x + threadIdx.x;
    if (idx >= BT * DD) return;
    int r = idx / DD, d = idx % DD;
    x[idx] = aemb[(size_t)act[r] * DD + d] + temb[d]
           + oemb[(size_t)obs[r] * DD + d] + temb[DD + d];
}

// ---------------- layernorm ----------------
__global__ void ln_kernel(const float* __restrict__ x, const float* __restrict__ g,
                          const float* __restrict__ b, float* __restrict__ y) {
    int r = blockIdx.x;
    const float* xr = x + (size_t)r * DD;
    float v[4];
    float s = 0.f, ss = 0.f;
#pragma unroll
    for (int i = 0; i < 4; i++) {
        float t = xr[threadIdx.x + i * 256];
        v[i] = t; s += t; ss += t * t;
    }
#pragma unroll
    for (int o = 16; o > 0; o >>= 1) {
        s  += __shfl_xor_sync(0xffffffffu, s,  o);
        ss += __shfl_xor_sync(0xffffffffu, ss, o);
    }
    __shared__ float rs[8], rss[8];
    int w = threadIdx.x >> 5;
    if ((threadIdx.x & 31) == 0) { rs[w] = s; rss[w] = ss; }
    __syncthreads();
    if (threadIdx.x == 0) {
        float a = 0.f, c = 0.f;
#pragma unroll
        for (int i = 0; i < 8; i++) { a += rs[i]; c += rss[i]; }
        rs[0] = a; rss[0] = c;
    }
    __syncthreads();
    float mean = rs[0] * (1.f / DD);
    float var  = rss[0] * (1.f / DD) - mean * mean;
    float inv  = rsqrtf(var + 1e-5f);
    float* yr = y + (size_t)r * DD;
#pragma unroll
    for (int i = 0; i < 4; i++) {
        int d = threadIdx.x + i * 256;
        yr[d] = (v[i] - mean) * inv * g[d] + b[d];
    }
}

// ---------------- RoPE via tables ----------------
__global__ void rope_kernel(float* __restrict__ Q, float* __restrict__ K,
                            const float* __restrict__ ct, const float* __restrict__ st) {
    int idx = blockIdx.x * blockDim.x + threadIdx.x;
    if (idx >= BT * (DD / 2)) return;
    int r  = idx / (DD / 2);
    int c2 = idx % (DD / 2);
    int p  = c2 & 31;
    int t  = r & (TT - 1);
    float c = ct[t * 32 + p];
    float s = st[t * 32 + p];
    size_t base = (size_t)r * DD + ((size_t)c2 << 1);
    float q0 = Q[base], q1 = Q[base + 1];
    Q[base]     = q0 * c - q1 * s;
    Q[base + 1] = q0 * s + q1 * c;
    float k0 = K[base], k1 = K[base + 1];
    K[base]     = k0 * c - k1 * s;
    K[base + 1] = k0 * s + k1 * c;
}

// ---------------- attention scores: 64x64 tiles, k-tile <= q-tile ----------------
__global__ __launch_bounds__(256)
void attn_scores_kernel(const float* __restrict__ Q, const float* __restrict__ K,
                        float* __restrict__ S) {
    int qt = blockIdx.x, kt = blockIdx.y, bh = blockIdx.z;
    if (kt > qt) return;
    int b = bh >> 4, h = bh & 15;
    const float* Qb = Q + ((size_t)b * TT + (size_t)qt * 64) * DD + h * 64;
    const float* Kb = K + ((size_t)b * TT + (size_t)kt * 64) * DD + h * 64;

    __shared__ float sQ[64][65];
    __shared__ float sK[64][65];
    int tid = threadIdx.x;
    int lr = tid >> 4;
    int lc = (tid & 15) << 2;
#pragma unroll
    for (int i = 0; i < 4; i++) {
        int row = lr + i * 16;
        float4 qv = *(const float4*)&Qb[(size_t)row * DD + lc];
        sQ[row][lc] = qv.x; sQ[row][lc + 1] = qv.y; sQ[row][lc + 2] = qv.z; sQ[row][lc + 3] = qv.w;
        float4 kv = *(const float4*)&Kb[(size_t)row * DD + lc];
        sK[row][lc] = kv.x; sK[row][lc + 1] = kv.y; sK[row][lc + 2] = kv.z; sK[row][lc + 3] = kv.w;
    }
    __syncthreads();

    int ty = (tid >> 4) << 2, tx = (tid & 15) << 2;
    float acc[4][4] = {};
#pragma unroll 8
    for (int d = 0; d < 64; d++) {
        float qv[4], kv[4];
#pragma unroll
        for (int j = 0; j < 4; j++) { qv[j] = sQ[ty + j][d]; kv[j] = sK[tx + j][d]; }
#pragma unroll
        for (int i = 0; i < 4; i++)
#pragma unroll
            for (int j = 0; j < 4; j++)
                acc[i][j] += qv[i] * kv[j];
    }
    float* Sp = S + ((size_t)bh * TT + (size_t)qt * 64) * TT + (size_t)kt * 64;
#pragma unroll
    for (int i = 0; i < 4; i++)
#pragma unroll
        for (int j = 0; j < 4; j++)
            Sp[(size_t)(ty + i) * TT + tx + j] = acc[i][j] * 0.125f;
}

// ---------------- causal softmax per row; zero-fills to tile boundary ----------------
__global__ void softmax_kernel(float* __restrict__ S) {
    int q = blockIdx.x, bh = blockIdx.y;
    float* row = S + ((size_t)bh * TT + q) * TT;
    int nv = q + 1;
    int kend = (q & ~63) + 64;
    int tid = threadIdx.x;

    __shared__ float red[8];

    float mx = -1e30f;
    for (int k = tid; k < nv; k += 256) mx = fmaxf(mx, row[k]);
#pragma unroll
    for (int o = 16; o > 0; o >>= 1) mx = fmaxf(mx, __shfl_xor_sync(0xffffffffu, mx, o));
    if ((tid & 31) == 0) red[tid >> 5] = mx;
    __syncthreads();
    if (tid == 0) {
        float m = red[0];
#pragma unroll
        for (int i = 1; i < 8; i++) m = fmaxf(m, red[i]);
        red[0] = m;
    }
    __syncthreads();
    float gmx = red[0];
    __syncthreads();

    float e[8];
    float sum = 0.f;
    int it = 0;
    for (int k = tid; k < nv; k += 256) {
        float ev = expf(row[k] - gmx);
        e[it++] = ev;
        sum += ev;
    }
#pragma unroll
    for (int o = 16; o > 0; o >>= 1) sum += __shfl_xor_sync(0xffffffffu, sum, o);
    if ((tid & 31) == 0) red[tid >> 5] = sum;
    __syncthreads();
    if (tid == 0) {
        float t = 0.f;
#pragma unroll
        for (int i = 0; i < 8; i++) t += red[i];
        red[0] = t;
    }
    __syncthreads();
    float invs = 1.f / red[0];

    it = 0;
    for (int k = tid; k < nv; k += 256)
        row[k] = e[it++] * invs;
    for (int k = nv + tid; k < kend; k += 256)
        row[k] = 0.f;
}

// ---------------- PV: 64q x 64d tiles ----------------
__global__ __launch_bounds__(256)
void attn_pv_kernel(const float* __restrict__ S, const float* __restrict__ V,
                    float* __restrict__ O) {
    int qt = blockIdx.x, bh = blockIdx.y;
    int b = bh >> 4, h = bh & 15;
    __shared__ float sP[64][65];
    __shared__ float sV[64][68];
    int tid = threadIdx.x;
    int lr = tid >> 4;
    int lc = (tid & 15) << 2;
    int ty = (tid >> 4) << 2, tx = (tid & 15) << 2;
    float acc[4][4] = {};

    const float* Srow = S + ((size_t)bh * TT + (size_t)qt * 64) * TT;
    const float* Vb = V + (size_t)b * TT * DD + h * 64;

    for (int kt = 0; kt <= qt; kt++) {
#pragma unroll
        for (int i = 0; i < 4; i++) {
            int row = lr + i * 16;
            float4 pv = *(const float4*)&Srow[(size_t)row * TT + (size_t)kt * 64 + lc];
            sP[row][lc] = pv.x; sP[row][lc + 1] = pv.y; sP[row][lc + 2] = pv.z; sP[row][lc + 3] = pv.w;
            float4 vv = *(const float4*)&Vb[(size_t)(kt * 64 + row) * DD + lc];
            *(float4*)&sV[row][lc] = vv;
        }
        __syncthreads();
#pragma unroll 8
        for (int kk = 0; kk < 64; kk++) {
            float p[4];
            float vv[4];
            *(float4*)vv = *(const float4*)&sV[kk][tx];
#pragma unroll
            for (int j = 0; j < 4; j++) p[j] = sP[ty + j][kk];
#pragma unroll
            for (int i = 0; i < 4; i++)
#pragma unroll
                for (int j = 0; j < 4; j++)
                    acc[i][j] += p[i] * vv[j];
        }
        __syncthreads();
    }

    float* Ob = O + ((size_t)b * TT + (size_t)qt * 64) * DD + h * 64;
#pragma unroll
    for (int i = 0; i < 4; i++)
#pragma unroll
        for (int j = 0; j < 4; j++)
            Ob[(size_t)(ty + i) * DD + tx + j] = acc[i][j];
}

// ---------------- host-side helpers ----------------
static void conv_A(const float* X, __nv_bfloat16* ah, __nv_bfloat16* al, int M, int K) {
    int n4 = M * K / 4;
    convA_kernel<<<(n4 + 255) / 256, 256>>>(X, ah, al, n4);
}
static void conv_B(const float* W, __nv_bfloat16* bh, __nv_bfloat16* bl, int K, int N) {
    convT_kernel<<<dim3(N / 32, K / 64), 256>>>(W, bh, bl, K, N);
}
template <int EPI>
static void gemm(const __nv_bfloat16* ah, const __nv_bfloat16* al,
                 const __nv_bfloat16* bh, const __nv_bfloat16* bl,
                 const float* bias, const float* R, float* C, int M, int N, int K) {
    static bool cfg = false;
    if (!cfg) {
        cudaFuncSetAttribute(gemm_mma<EPI>, cudaFuncAttributeMaxDynamicSharedMemorySize, GSMEM);
        cfg = true;
    }
    gemm_mma<EPI><<<dim3(N / 128, M / 128), 256, GSMEM>>>(ah, al, bh, bl, bias, R, C, M, N, K);
}

// ---------------- launch sequence ----------------
extern "C" void kernel_launch(void* const* d_in, const int* in_sizes, int n_in,
                              void* d_out, int out_size) {
    const int*   actions = (const int*)d_in[0];
    const int*   observ  = (const int*)d_in[1];
    const float* aemb    = (const float*)d_in[2];
    const float* oemb    = (const float*)d_in[3];
    const float* temb    = (const float*)d_in[4];
    const float* Wq      = (const float*)d_in[5];
    const float* bq      = (const float*)d_in[6];
    const float* Wk      = (const float*)d_in[7];
    const float* bk      = (const float*)d_in[8];
    const float* Wv      = (const float*)d_in[9];
    const float* bv      = (const float*)d_in[10];
    const float* Wo      = (const float*)d_in[11];
    const float* bo      = (const float*)d_in[12];
    const float* ln1_g   = (const float*)d_in[13];
    const float* ln1_b   = (const float*)d_in[14];
    const float* ln2_g   = (const float*)d_in[15];
    const float* ln2_b   = (const float*)d_in[16];
    const float* W1      = (const float*)d_in[17];
    const float* b1      = (const float*)d_in[18];
    const float* W2      = (const float*)d_in[19];
    const float* b2      = (const float*)d_in[20];
    const float* out_g   = (const float*)d_in[21];
    const float* out_b   = (const float*)d_in[22];
    const float* Wout    = (const float*)d_in[23];
    const float* bout    = (const float*)d_in[24];

    float *x, *h, *q, *k, *v, *o, *ff, *S, *ct, *st;
    __nv_bfloat16 *ah, *al, *bh, *bl;
    cudaGetSymbolAddress((void**)&x,  g_x);
    cudaGetSymbolAddress((void**)&h,  g_h);
    cudaGetSymbolAddress((void**)&q,  g_q);
    cudaGetSymbolAddress((void**)&k,  g_k);
    cudaGetSymbolAddress((void**)&v,  g_v);
    cudaGetSymbolAddress((void**)&o,  g_o);
    cudaGetSymbolAddress((void**)&ff, g_ff);
    cudaGetSymbolAddress((void**)&S,  g_S);
    cudaGetSymbolAddress((void**)&ct, g_cos);
    cudaGetSymbolAddress((void**)&st, g_sin);
    cudaGetSymbolAddress((void**)&ah, g_ah);
    cudaGetSymbolAddress((void**)&al, g_al);
    cudaGetSymbolAddress((void**)&bh, g_bh);
    cudaGetSymbolAddress((void**)&bl, g_bl);

    trig_kernel<<<(TT * 32 + 255) / 256, 256>>>(ct, st);
    embed_kernel<<<(BT * DD + 255) / 256, 256>>>(actions, observ, aemb, oemb, temb, x);

    for (int i = 0; i < LL; i++) {
        ln_kernel<<<BT, 256>>>(x, ln1_g + (size_t)i * DD, ln1_b + (size_t)i * DD, h);
        conv_A(h, ah, al, BT, DD);

        conv_B(Wq + (size_t)i * DD * DD, bh, bl, DD, DD);
        gemm<0>(ah, al, bh, bl, bq + (size_t)i * DD, nullptr, q, BT, DD, DD);
        conv_B(Wk + (size_t)i * DD * DD, bh, bl, DD, DD);
        gemm<0>(ah, al, bh, bl, bk + (size_t)i * DD, nullptr, k, BT, DD, DD);
        conv_B(Wv + (size_t)i * DD * DD, bh, bl, DD, DD);
        gemm<0>(ah, al, bh, bl, bv + (size_t)i * DD, nullptr, v, BT, DD, DD);

        rope_kernel<<<(BT * (DD / 2) + 255) / 256, 256>>>(q, k, ct, st);

        attn_scores_kernel<<<dim3(TT / 64, TT / 64, BB * HH), 256>>>(q, k, S);
        softmax_kernel<<<dim3(TT, BB * HH), 256>>>(S);
        attn_pv_kernel<<<dim3(TT / 64, BB * HH), 256>>>(S, v, o);

        conv_A(o, ah, al, BT, DD);
        conv_B(Wo + (size_t)i * DD * DD, bh, bl, DD, DD);
        gemm<2>(ah, al, bh, bl, bo + (size_t)i * DD, x, x, BT, DD, DD);

        ln_kernel<<<BT, 256>>>(x, ln2_g + (size_t)i * DD, ln2_b + (size_t)i * DD, h);
        conv_A(h, ah, al, BT, DD);
        conv_B(W1 + (size_t)i * DD * DFF, bh, bl, DD, DFF);
        gemm<1>(ah, al, bh, bl, b1 + (size_t)i * DFF, nullptr, ff, BT, DFF, DD);

        conv_A(ff, ah, al, BT, DFF);
        conv_B(W2 + (size_t)i * DFF * DD, bh, bl, DFF, DD);
        gemm<2>(ah, al, bh, bl, b2 + (size_t)i * DD, x, x, BT, DD, DFF);
    }

    ln_kernel<<<BT, 256>>>(x, out_g, out_b, h);
    conv_A(h, ah, al, BT, DD);
    conv_B(Wout, bh, bl, DD, OV);
    gemm<0>(ah, al, bh, bl, bout, nullptr, (float*)d_out, BT, OV, DD);
}

// round 8
// speedup vs baseline: 3.2507x; 1.2729x over previous
#include <cuda_runtime.h>
#include <cuda_bf16.h>
#include <math.h>
#include <stdint.h>

#define LL 2
#define DD 1024
#define HH 16
#define DHH 64
#define DFF 4096
#define BB 2
#define TT 2048
#define OV 4096
#define BT (BB*TT)   // 4096

// ---------------- scratch (device globals; no runtime allocation) ----------------
__device__ float g_x [BT*DD];
__device__ float g_h [BT*DD];
__device__ float g_q [BT*DD];
__device__ float g_k [BT*DD];
__device__ float g_v [BT*DD];
__device__ float g_o [BT*DD];
__device__ float g_ff[BT*DFF];
__device__ float g_S [(size_t)BB*HH*TT*TT];   // 512 MB score / prob scratch
__device__ float g_cos[TT*32];
__device__ float g_sin[TT*32];
// bf16 split operands (16B-aligned for vector access)
__device__ __align__(16) __nv_bfloat16 g_ah[(size_t)BT*DFF];   // A hi
__device__ __align__(16) __nv_bfloat16 g_al[(size_t)BT*DFF];   // A lo
__device__ __align__(16) __nv_bfloat16 g_bh[(size_t)DFF*DD];   // B^T hi  [N,K]
__device__ __align__(16) __nv_bfloat16 g_bl[(size_t)DFF*DD];   // B^T lo
// attention split operands
__device__ __align__(16) __nv_bfloat16 g_qh[(size_t)BB*HH*TT*DHH];  // [bh][t][d]
__device__ __align__(16) __nv_bfloat16 g_ql[(size_t)BB*HH*TT*DHH];
__device__ __align__(16) __nv_bfloat16 g_kh[(size_t)BB*HH*TT*DHH];
__device__ __align__(16) __nv_bfloat16 g_kl[(size_t)BB*HH*TT*DHH];
__device__ __align__(16) __nv_bfloat16 g_vh[(size_t)BB*HH*DHH*TT];  // [bh][d][t]
__device__ __align__(16) __nv_bfloat16 g_vl[(size_t)BB*HH*DHH*TT];

// ---------------- warp-MMA primitives (baseline PTX; no sm_103a features) ----------
__device__ __forceinline__ uint32_t smem_u32(const void* p) {
    uint32_t a;
    asm("{ .reg .u64 t; cvta.to.shared.u64 t, %1; cvt.u32.u64 %0, t; }" : "=r"(a) : "l"(p));
    return a;
}
__device__ __forceinline__ void ldm4(uint32_t* r, uint32_t addr) {
    asm volatile("ldmatrix.sync.aligned.m8n8.x4.shared.b16 {%0,%1,%2,%3}, [%4];"
                 : "=r"(r[0]), "=r"(r[1]), "=r"(r[2]), "=r"(r[3]) : "r"(addr));
}
__device__ __forceinline__ void mma16816(float* d, const uint32_t* a, const uint32_t* b) {
    asm volatile("mma.sync.aligned.m16n8k16.row.col.f32.bf16.bf16.f32 "
                 "{%0,%1,%2,%3}, {%4,%5,%6,%7}, {%8,%9}, {%0,%1,%2,%3};"
                 : "+f"(d[0]), "+f"(d[1]), "+f"(d[2]), "+f"(d[3])
                 : "r"(a[0]), "r"(a[1]), "r"(a[2]), "r"(a[3]), "r"(b[0]), "r"(b[1]));
}
#define CPA(dst, src) asm volatile("cp.async.cg.shared.global [%0], [%1], 16;" :: "r"(dst), "l"(src))
#define CPC()         asm volatile("cp.async.commit_group;")
#define CPW(n)        asm volatile("cp.async.wait_group %0;" :: "n"(n))

__device__ __forceinline__ uint32_t bfpack(float x, float y) {
    __nv_bfloat162 t;
    t.x = __float2bfloat16_rn(x);
    t.y = __float2bfloat16_rn(y);
    return *(uint32_t*)&t;
}

// ---------------- split-precision conversion: A (row-major passthrough) ----------------
__global__ void convA_kernel(const float* __restrict__ X, __nv_bfloat16* __restrict__ hi,
                             __nv_bfloat16* __restrict__ lo, int n4) {
    int i = blockIdx.x * 256 + threadIdx.x;
    if (i >= n4) return;
    float4 v = ((const float4*)X)[i];
    __nv_bfloat16 h0 = __float2bfloat16_rn(v.x), h1 = __float2bfloat16_rn(v.y);
    __nv_bfloat16 h2 = __float2bfloat16_rn(v.z), h3 = __float2bfloat16_rn(v.w);
    __nv_bfloat162 H0; H0.x = h0; H0.y = h1;
    __nv_bfloat162 H1; H1.x = h2; H1.y = h3;
    __nv_bfloat162 L0, L1;
    L0.x = __float2bfloat16_rn(v.x - __bfloat162float(h0));
    L0.y = __float2bfloat16_rn(v.y - __bfloat162float(h1));
    L1.x = __float2bfloat16_rn(v.z - __bfloat162float(h2));
    L1.y = __float2bfloat16_rn(v.w - __bfloat162float(h3));
    ((__nv_bfloat162*)hi)[2*i]     = H0;
    ((__nv_bfloat162*)hi)[2*i + 1] = H1;
    ((__nv_bfloat162*)lo)[2*i]     = L0;
    ((__nv_bfloat162*)lo)[2*i + 1] = L1;
}

// ---------------- split + transpose: W[K,N] -> Bt[N,K] hi/lo ----------------
__global__ void convT_kernel(const float* __restrict__ W, __nv_bfloat16* __restrict__ ht,
                             __nv_bfloat16* __restrict__ lt, int K, int N) {
    __shared__ float t[64][33];
    int n0 = blockIdx.x * 32, k0 = blockIdx.y * 64;
    int tx = threadIdx.x & 31, ty = threadIdx.x >> 5;
#pragma unroll
    for (int ky = 0; ky < 64; ky += 8)
        t[ky + ty][tx] = W[(size_t)(k0 + ky + ty) * N + n0 + tx];
    __syncthreads();
    int kl = threadIdx.x & 63, nb = threadIdx.x >> 6;
#pragma unroll
    for (int n = nb; n < 32; n += 4) {
        float v = t[kl][n];
        __nv_bfloat16 h = __float2bfloat16_rn(v);
        size_t o = (size_t)(n0 + n) * K + k0 + kl;
        ht[o] = h;
        lt[o] = __float2bfloat16_rn(v - __bfloat162float(h));
    }
}

// ---------------- HMMA split-bf16 GEMM, cp.async double-buffered ----------------
// A: (Ahi,Alo)[M,K] row-major; B: (Bhi,Blo)[N,K] row-major.
// 128x128 CTA tile, 8 warps (2x4), warp tile 64x32, K-chunk 64, 2 stages.
#define TROW 72
#define TBYTES (128*TROW*2)      // 18432 per tile
#define GSMEM (2*4*TBYTES)       // 147456

template <int EPI>
__global__ __launch_bounds__(256)
void gemm_mma(const __nv_bfloat16* __restrict__ Ahi, const __nv_bfloat16* __restrict__ Alo,
              const __nv_bfloat16* __restrict__ Bhi, const __nv_bfloat16* __restrict__ Blo,
              const float* __restrict__ bias, const float* __restrict__ R,
              float* __restrict__ C, int M, int N, int K) {
    extern __shared__ __align__(16) char smem[];
    const uint32_t sb = smem_u32(smem);
    int tid = threadIdx.x, lane = tid & 31, w = tid >> 5;
    int wm = w >> 2, wn = w & 3;
    int bm = blockIdx.y << 7, bn = blockIdx.x << 7;

    float acc[4][4][4];
#pragma unroll
    for (int i = 0; i < 4; i++)
#pragma unroll
        for (int j = 0; j < 4; j++)
#pragma unroll
            for (int z = 0; z < 4; z++) acc[i][j][z] = 0.f;

    int lrow = tid >> 3, lseg = tid & 7;
    auto issue = [&](int kc, int st) {
        int kb = kc << 6;
        uint32_t base = sb + st * 4 * TBYTES;
#pragma unroll
        for (int i = 0; i < 4; i++) {
            int row = lrow + i * 32;
            uint32_t so = base + (uint32_t)(row * 144 + lseg * 16);
            size_t ga = (size_t)(bm + row) * K + kb + lseg * 8;
            size_t gb = (size_t)(bn + row) * K + kb + lseg * 8;
            CPA(so,              Ahi + ga);
            CPA(so + TBYTES,     Alo + ga);
            CPA(so + 2*TBYTES,   Bhi + gb);
            CPA(so + 3*TBYTES,   Blo + gb);
        }
        CPC();
    };

    const int nch = K >> 6;
    issue(0, 0);

    int a_row = wm * 64 + (lane & 15), a_col = (lane >> 4) << 3;
    int b_row = wn * 32 + ((lane >> 4) << 3) + (lane & 7), b_col = ((lane >> 3) & 1) << 3;
    uint32_t aoff = (uint32_t)(a_row * TROW + a_col) * 2;
    uint32_t boff = (uint32_t)(b_row * TROW + b_col) * 2 + 2 * TBYTES;

    for (int kc = 0; kc < nch; kc++) {
        if (kc + 1 < nch) { issue(kc + 1, (kc + 1) & 1); CPW(1); }
        else              { CPW(0); }
        __syncthreads();
        uint32_t base = sb + (kc & 1) * 4 * TBYTES;
        uint32_t aoff_h = base + aoff, aoff_l = aoff_h + TBYTES;
        uint32_t boff_h = base + boff, boff_l = boff_h + TBYTES;
#pragma unroll
        for (int ks = 0; ks < 4; ks++) {
            uint32_t ah[4][4], al[4][4], bh[8], bl[8];
            uint32_t kso = (uint32_t)(ks * 32);
#pragma unroll
            for (int mi = 0; mi < 4; mi++) {
                ldm4(ah[mi], aoff_h + (uint32_t)(mi * 16 * TROW * 2) + kso);
                ldm4(al[mi], aoff_l + (uint32_t)(mi * 16 * TROW * 2) + kso);
            }
            ldm4(&bh[0], boff_h + kso);
            ldm4(&bh[4], boff_h + (uint32_t)(16 * TROW * 2) + kso);
#pragma unroll
            for (int mi = 0; mi < 4; mi++)
#pragma unroll
                for (int ni = 0; ni < 4; ni++)
                    mma16816(acc[mi][ni], ah[mi], &bh[ni * 2]);
#pragma unroll
            for (int mi = 0; mi < 4; mi++)
#pragma unroll
                for (int ni = 0; ni < 4; ni++)
                    mma16816(acc[mi][ni], al[mi], &bh[ni * 2]);
            ldm4(&bl[0], boff_l + kso);
            ldm4(&bl[4], boff_l + (uint32_t)(16 * TROW * 2) + kso);
#pragma unroll
            for (int mi = 0; mi < 4; mi++)
#pragma unroll
                for (int ni = 0; ni < 4; ni++)
                    mma16816(acc[mi][ni], ah[mi], &bl[ni * 2]);
        }
        __syncthreads();
    }

    // ---- epilogue: direct to global ----
#pragma unroll
    for (int mi = 0; mi < 4; mi++) {
#pragma unroll
        for (int ni = 0; ni < 4; ni++) {
            int r0 = bm + wm * 64 + mi * 16 + (lane >> 2);
            int c0 = bn + wn * 32 + ni * 8 + ((lane & 3) << 1);
#pragma unroll
            for (int half = 0; half < 2; half++) {
                int gm = r0 + half * 8;
                float v0 = acc[mi][ni][half * 2]     + bias[c0];
                float v1 = acc[mi][ni][half * 2 + 1] + bias[c0 + 1];
                if (EPI == 1) { v0 *= normcdff(v0); v1 *= normcdff(v1); }
                if (EPI == 2) {
                    v0 += R[(size_t)gm * N + c0];
                    v1 += R[(size_t)gm * N + c0 + 1];
                }
                float2 o; o.x = v0; o.y = v1;
                *(float2*)&C[(size_t)gm * N + c0] = o;
            }
        }
    }
}

// ---------------- RoPE trig tables (double precision; fast-math-proof) ----------------
__global__ void trig_kernel(float* __restrict__ ct, float* __restrict__ st) {
    int i = blockIdx.x * 256 + threadIdx.x;
    if (i >= TT * 32) return;
    int t = i >> 5, p = i & 31;
    double inv = exp2(-13.287712379549449 * ((double)(2 * p) * (1.0 / 64.0)));
    float invf = (float)inv;
    float angf = (float)((double)t * (double)invf);
    double c, s;
    sincos((double)angf, &s, &c);
    ct[i] = (float)c;
    st[i] = (float)s;
}

// ---------------- embedding ----------------
__global__ void embed_kernel(const int* __restrict__ act, const int* __restrict__ obs,
                             const float* __restrict__ aemb, const float* __restrict__ oemb,
                             const float* __restrict__ temb, float* __restrict__ x) {
    int idx = blockIdx.x * blockDim.x + threadIdx.x;
    if (idx >= BT * DD) return;
    int r = idx / DD, d = idx % DD;
    x[idx] = aemb[(size_t)act[r] * DD + d] + temb[d]
           + oemb[(size_t)obs[r] * DD + d] + temb[DD + d];
}

// ---------------- layernorm ----------------
__global__ void ln_kernel(const float* __restrict__ x, const float* __restrict__ g,
                          const float* __restrict__ b, float* __restrict__ y) {
    int r = blockIdx.x;
    const float* xr = x + (size_t)r * DD;
    float v[4];
    float s = 0.f, ss = 0.f;
#pragma unroll
    for (int i = 0; i < 4; i++) {
        float t = xr[threadIdx.x + i * 256];
        v[i] = t; s += t; ss += t * t;
    }
#pragma unroll
    for (int o = 16; o > 0; o >>= 1) {
        s  += __shfl_xor_sync(0xffffffffu, s,  o);
        ss += __shfl_xor_sync(0xffffffffu, ss, o);
    }
    __shared__ float rs[8], rss[8];
    int w = threadIdx.x >> 5;
    if ((threadIdx.x & 31) == 0) { rs[w] = s; rss[w] = ss; }
    __syncthreads();
    if (threadIdx.x == 0) {
        float a = 0.f, c = 0.f;
#pragma unroll
        for (int i = 0; i < 8; i++) { a += rs[i]; c += rss[i]; }
        rs[0] = a; rss[0] = c;
    }
    __syncthreads();
    float mean = rs[0] * (1.f / DD);
    float var  = rss[0] * (1.f / DD) - mean * mean;
    float inv  = rsqrtf(var + 1e-5f);
    float* yr = y + (size_t)r * DD;
#pragma unroll
    for (int i = 0; i < 4; i++) {
        int d = threadIdx.x + i * 256;
        yr[d] = (v[i] - mean) * inv * g[d] + b[d];
    }
}

// ---------------- RoPE + hi/lo split into per-head layout [bh][t][64] ----------------
__global__ void rope_split_kernel(const float* __restrict__ Q, const float* __restrict__ K,
                                  const float* __restrict__ ct, const float* __restrict__ st,
                                  __nv_bfloat16* __restrict__ qh, __nv_bfloat16* __restrict__ ql,
                                  __nv_bfloat16* __restrict__ kh, __nv_bfloat16* __restrict__ kl) {
    int idx = blockIdx.x * 256 + threadIdx.x;
    if (idx >= BT * (DD / 2)) return;
    int r  = idx >> 9;           // row in [BT]
    int c2 = idx & 511;
    int hh = c2 >> 5, p = c2 & 31;
    int b = r >> 11, t = r & (TT - 1);
    float c = ct[t * 32 + p];
    float s = st[t * 32 + p];
    size_t ib = (size_t)r * DD + hh * 64 + 2 * p;
    size_t ob = ((size_t)(b * HH + hh) * TT + t) * 64 + 2 * p;

    float q0 = Q[ib], q1 = Q[ib + 1];
    float o0 = q0 * c - q1 * s, o1 = q0 * s + q1 * c;
    __nv_bfloat16 h0 = __float2bfloat16_rn(o0), h1 = __float2bfloat16_rn(o1);
    qh[ob] = h0; qh[ob + 1] = h1;
    ql[ob]     = __float2bfloat16_rn(o0 - __bfloat162float(h0));
    ql[ob + 1] = __float2bfloat16_rn(o1 - __bfloat162float(h1));

    float k0 = K[ib], k1 = K[ib + 1];
    float e0 = k0 * c - k1 * s, e1 = k0 * s + k1 * c;
    __nv_bfloat16 g0 = __float2bfloat16_rn(e0), g1 = __float2bfloat16_rn(e1);
    kh[ob] = g0; kh[ob + 1] = g1;
    kl[ob]     = __float2bfloat16_rn(e0 - __bfloat162float(g0));
    kl[ob + 1] = __float2bfloat16_rn(e1 - __bfloat162float(g1));
}

// ---------------- V split + transpose into [bh][d][t] ----------------
__global__ void vsplit_kernel(const float* __restrict__ V,
                              __nv_bfloat16* __restrict__ vh, __nv_bfloat16* __restrict__ vl) {
    __shared__ float ts[32][33];
    int t0 = blockIdx.x * 32, d0 = blockIdx.y * 32, b = blockIdx.z;
    int tx = threadIdx.x & 31, ty = threadIdx.x >> 5;
#pragma unroll
    for (int i = ty; i < 32; i += 8)
        ts[i][tx] = V[((size_t)b * TT + t0 + i) * DD + d0 + tx];   // ts[t-local][d-local]
    __syncthreads();
    int hh = d0 >> 6, dl0 = d0 & 63;
#pragma unroll
    for (int i = ty; i < 32; i += 8) {
        float v = ts[tx][i];    // = V[t0+tx][d0+i]
        size_t o = ((size_t)(b * HH + hh) * 64 + dl0 + i) * TT + t0 + tx;
        __nv_bfloat16 h = __float2bfloat16_rn(v);
        vh[o] = h;
        vl[o] = __float2bfloat16_rn(v - __bfloat162float(h));
    }
}

// ---------------- HMMA scores: 128x128 tiles, S = (Q K^T)/8 ----------------
__global__ __launch_bounds__(256)
void attn_scores_mma(const __nv_bfloat16* __restrict__ Qh, const __nv_bfloat16* __restrict__ Ql,
                     const __nv_bfloat16* __restrict__ Kh, const __nv_bfloat16* __restrict__ Kl,
                     float* __restrict__ S) {
    int qt = blockIdx.x, kt = blockIdx.y, bh = blockIdx.z;
    if (kt > qt) return;
    extern __shared__ __align__(16) char smem[];
    const uint32_t sb = smem_u32(smem);
    int tid = threadIdx.x, lane = tid & 31, w = tid >> 5;
    int wm = w >> 2, wn = w & 3;

    // load 4 tiles: 128 rows x 64 bf16 (128B/row) at pitch 144B
    {
        int row = tid >> 1, segb = (tid & 1) * 4;
        size_t qg = ((size_t)bh * TT + qt * 128 + row) * 64 + segb * 8;
        size_t kg = ((size_t)bh * TT + kt * 128 + row) * 64 + segb * 8;
#pragma unroll
        for (int s = 0; s < 4; s++) {
            uint32_t so = (uint32_t)(row * 144 + (segb + s) * 16);
            *(uint4*)(smem + so)              = *(const uint4*)(Qh + qg + s * 8);
            *(uint4*)(smem + so + TBYTES)     = *(const uint4*)(Ql + qg + s * 8);
            *(uint4*)(smem + so + 2*TBYTES)   = *(const uint4*)(Kh + kg + s * 8);
            *(uint4*)(smem + so + 3*TBYTES)   = *(const uint4*)(Kl + kg + s * 8);
        }
    }
    __syncthreads();

    float acc[4][4][4];
#pragma unroll
    for (int i = 0; i < 4; i++)
#pragma unroll
        for (int j = 0; j < 4; j++)
#pragma unroll
            for (int z = 0; z < 4; z++) acc[i][j][z] = 0.f;

    int a_row = wm * 64 + (lane & 15), a_col = (lane >> 4) << 3;
    int b_row = wn * 32 + ((lane >> 4) << 3) + (lane & 7), b_col = ((lane >> 3) & 1) << 3;
    uint32_t aoff_h = sb + (uint32_t)(a_row * TROW + a_col) * 2, aoff_l = aoff_h + TBYTES;
    uint32_t boff_h = sb + 2 * TBYTES + (uint32_t)(b_row * TROW + b_col) * 2, boff_l = boff_h + TBYTES;
#pragma unroll
    for (int ks = 0; ks < 4; ks++) {
        uint32_t ah[4][4], al[4][4], bh8[8], bl8[8];
        uint32_t kso = (uint32_t)(ks * 32);
#pragma unroll
        for (int mi = 0; mi < 4; mi++) {
            ldm4(ah[mi], aoff_h + (uint32_t)(mi * 16 * TROW * 2) + kso);
            ldm4(al[mi], aoff_l + (uint32_t)(mi * 16 * TROW * 2) + kso);
        }
        ldm4(&bh8[0], boff_h + kso);
        ldm4(&bh8[4], boff_h + (uint32_t)(16 * TROW * 2) + kso);
#pragma unroll
        for (int mi = 0; mi < 4; mi++)
#pragma unroll
            for (int ni = 0; ni < 4; ni++)
                mma16816(acc[mi][ni], ah[mi], &bh8[ni * 2]);
#pragma unroll
        for (int mi = 0; mi < 4; mi++)
#pragma unroll
            for (int ni = 0; ni < 4; ni++)
                mma16816(acc[mi][ni], al[mi], &bh8[ni * 2]);
        ldm4(&bl8[0], boff_l + kso);
        ldm4(&bl8[4], boff_l + (uint32_t)(16 * TROW * 2) + kso);
#pragma unroll
        for (int mi = 0; mi < 4; mi++)
#pragma unroll
            for (int ni = 0; ni < 4; ni++)
                mma16816(acc[mi][ni], ah[mi], &bl8[ni * 2]);
    }

    float* Sb = S + (size_t)bh * TT * TT;
#pragma unroll
    for (int mi = 0; mi < 4; mi++) {
#pragma unroll
        for (int ni = 0; ni < 4; ni++) {
            int r0 = qt * 128 + wm * 64 + mi * 16 + (lane >> 2);
            int c0 = kt * 128 + wn * 32 + ni * 8 + ((lane & 3) << 1);
#pragma unroll
            for (int half = 0; half < 2; half++) {
                int r = r0 + half * 8;
                float2 o;
                o.x = acc[mi][ni][half * 2]     * 0.125f;
                o.y = acc[mi][ni][half * 2 + 1] * 0.125f;
                *(float2*)&Sb[(size_t)r * TT + c0] = o;
            }
        }
    }
}

// ---------------- causal softmax per row; zero-fills to 128-tile boundary ----------------
__global__ void softmax_kernel(float* __restrict__ S) {
    int q = blockIdx.x, bh = blockIdx.y;
    float* row = S + ((size_t)bh * TT + q) * TT;
    int nv = q + 1;
    int kend = (q & ~127) + 128;
    int tid = threadIdx.x;

    __shared__ float red[8];

    float mx = -1e30f;
    for (int k = tid; k < nv; k += 256) mx = fmaxf(mx, row[k]);
#pragma unroll
    for (int o = 16; o > 0; o >>= 1) mx = fmaxf(mx, __shfl_xor_sync(0xffffffffu, mx, o));
    if ((tid & 31) == 0) red[tid >> 5] = mx;
    __syncthreads();
    if (tid == 0) {
        float m = red[0];
#pragma unroll
        for (int i = 1; i < 8; i++) m = fmaxf(m, red[i]);
        red[0] = m;
    }
    __syncthreads();
    float gmx = red[0];
    __syncthreads();

    float e[8];
    float sum = 0.f;
    int it = 0;
    for (int k = tid; k < nv; k += 256) {
        float ev = expf(row[k] - gmx);
        e[it++] = ev;
        sum += ev;
    }
#pragma unroll
    for (int o = 16; o > 0; o >>= 1) sum += __shfl_xor_sync(0xffffffffu, sum, o);
    if ((tid & 31) == 0) red[tid >> 5] = sum;
    __syncthreads();
    if (tid == 0) {
        float t = 0.f;
#pragma unroll
        for (int i = 0; i < 8; i++) t += red[i];
        red[0] = t;
    }
    __syncthreads();
    float invs = 1.f / red[0];

    it = 0;
    for (int k = tid; k < nv; k += 256)
        row[k] = e[it++] * invs;
    for (int k = nv + tid; k < kend; k += 256)
        row[k] = 0.f;
}

// ---------------- HMMA PV: O[128q,64d] = sum_kt P-tile @ V-tile ----------------
#define PROW 136
#define PTB (128*PROW*2)        // 34816
#define VTB (64*PROW*2)         // 17408
#define PVSMEM (2*PTB + 2*VTB)  // 104448

__global__ __launch_bounds__(256)
void attn_pv_mma(const float* __restrict__ S, const __nv_bfloat16* __restrict__ Vh,
                 const __nv_bfloat16* __restrict__ Vl, float* __restrict__ O) {
    int qt = blockIdx.x, bh = blockIdx.y;
    int b = bh >> 4, hh = bh & 15;
    extern __shared__ __align__(16) char smem[];
    const uint32_t sb = smem_u32(smem);
    int tid = threadIdx.x, lane = tid & 31, w = tid >> 5;
    int wm = w >> 1, wn = w & 1;     // 4x2 warps, warp tile 32x32

    float acc[2][4][4];
#pragma unroll
    for (int i = 0; i < 2; i++)
#pragma unroll
        for (int j = 0; j < 4; j++)
#pragma unroll
            for (int z = 0; z < 4; z++) acc[i][j][z] = 0.f;

    int prow = tid >> 1, pc0 = (tid & 1) * 64;
    int vrow = tid >> 2, vsegb = (tid & 3) * 4;

    int a_row = wm * 32 + (lane & 15), a_col = (lane >> 4) << 3;
    int b_row = wn * 32 + ((lane >> 4) << 3) + (lane & 7), b_col = ((lane >> 3) & 1) << 3;
    uint32_t aoff_h = sb + (uint32_t)(a_row * PROW + a_col) * 2, aoff_l = aoff_h + PTB;
    uint32_t boff_h = sb + 2 * PTB + (uint32_t)(b_row * PROW + b_col) * 2, boff_l = boff_h + VTB;

    for (int kt = 0; kt <= qt; kt++) {
        // V tiles: 64 rows (d) x 128 bf16 (t) at pitch 272B
        size_t vg = ((size_t)bh * 64 + vrow) * TT + kt * 128 + vsegb * 8;
#pragma unroll
        for (int s = 0; s < 4; s++) {
            uint32_t so = (uint32_t)(vrow * PROW * 2 + (vsegb + s) * 16);
            *(uint4*)(smem + 2*PTB + so)       = *(const uint4*)(Vh + vg + s * 8);
            *(uint4*)(smem + 2*PTB + VTB + so) = *(const uint4*)(Vl + vg + s * 8);
        }
        // P tile: load fp32, split to hi/lo bf16
        const float4* Sp = (const float4*)(S + ((size_t)bh * TT + qt * 128 + prow) * TT + kt * 128 + pc0);
        uint32_t po = (uint32_t)(prow * PROW * 2 + pc0 * 2);
#pragma unroll
        for (int j = 0; j < 16; j++) {
            float4 p = Sp[j];
            __nv_bfloat16 hx = __float2bfloat16_rn(p.x), hy = __float2bfloat16_rn(p.y);
            __nv_bfloat16 hz = __float2bfloat16_rn(p.z), hw = __float2bfloat16_rn(p.w);
            uint2 H, L;
            __nv_bfloat162 t0; t0.x = hx; t0.y = hy;
            __nv_bfloat162 t1; t1.x = hz; t1.y = hw;
            H.x = *(uint32_t*)&t0; H.y = *(uint32_t*)&t1;
            L.x = bfpack(p.x - __bfloat162float(hx), p.y - __bfloat162float(hy));
            L.y = bfpack(p.z - __bfloat162float(hz), p.w - __bfloat162float(hw));
            *(uint2*)(smem + po + j * 8)       = H;
            *(uint2*)(smem + PTB + po + j * 8) = L;
        }
        __syncthreads();

#pragma unroll
        for (int ks = 0; ks < 8; ks++) {
            uint32_t ph[2][4], pl[2][4], vh8[8], vl8[8];
            uint32_t kso = (uint32_t)(ks * 32);
#pragma unroll
            for (int mi = 0; mi < 2; mi++) {
                ldm4(ph[mi], aoff_h + (uint32_t)(mi * 16 * PROW * 2) + kso);
                ldm4(pl[mi], aoff_l + (uint32_t)(mi * 16 * PROW * 2) + kso);
            }
            ldm4(&vh8[0], boff_h + kso);
            ldm4(&vh8[4], boff_h + (uint32_t)(16 * PROW * 2) + kso);
#pragma unroll
            for (int mi = 0; mi < 2; mi++)
#pragma unroll
                for (int ni = 0; ni < 4; ni++)
                    mma16816(acc[mi][ni], ph[mi], &vh8[ni * 2]);
#pragma unroll
            for (int mi = 0; mi < 2; mi++)
#pragma unroll
                for (int ni = 0; ni < 4; ni++)
                    mma16816(acc[mi][ni], pl[mi], &vh8[ni * 2]);
            ldm4(&vl8[0], boff_l + kso);
            ldm4(&vl8[4], boff_l + (uint32_t)(16 * PROW * 2) + kso);
#pragma unroll
            for (int mi = 0; mi < 2; mi++)
#pragma unroll
                for (int ni = 0; ni < 4; ni++)
                    mma16816(acc[mi][ni], ph[mi], &vl8[ni * 2]);
        }
        __syncthreads();
    }

    // epilogue: back to [b][t][h*64+d] fp32
#pragma unroll
    for (int mi = 0; mi < 2; mi++) {
#pragma unroll
        for (int ni = 0; ni < 4; ni++) {
            int r0 = qt * 128 + wm * 32 + mi * 16 + (lane >> 2);
            int c0 = wn * 32 + ni * 8 + ((lane & 3) << 1);
#pragma unroll
            for (int half = 0; half < 2; half++) {
                int r = r0 + half * 8;
                float2 o;
                o.x = acc[mi][ni][half * 2];
                o.y = acc[mi][ni][half * 2 + 1];
                *(float2*)&O[((size_t)b * TT + r) * DD + hh * 64 + c0] = o;
            }
        }
    }
}

// ---------------- host-side helpers ----------------
static void conv_A(const float* X, __nv_bfloat16* ah, __nv_bfloat16* al, int M, int K) {
    int n4 = M * K / 4;
    convA_kernel<<<(n4 + 255) / 256, 256>>>(X, ah, al, n4);
}
static void conv_B(const float* W, __nv_bfloat16* bh, __nv_bfloat16* bl, int K, int N) {
    convT_kernel<<<dim3(N / 32, K / 64), 256>>>(W, bh, bl, K, N);
}
template <int EPI>
static void gemm(const __nv_bfloat16* ah, const __nv_bfloat16* al,
                 const __nv_bfloat16* bh, const __nv_bfloat16* bl,
                 const float* bias, const float* R, float* C, int M, int N, int K) {
    static bool cfg = false;
    if (!cfg) {
        cudaFuncSetAttribute(gemm_mma<EPI>, cudaFuncAttributeMaxDynamicSharedMemorySize, GSMEM);
        cfg = true;
    }
    gemm_mma<EPI><<<dim3(N / 128, M / 128), 256, GSMEM>>>(ah, al, bh, bl, bias, R, C, M, N, K);
}

// ---------------- launch sequence ----------------
extern "C" void kernel_launch(void* const* d_in, const int* in_sizes, int n_in,
                              void* d_out, int out_size) {
    const int*   actions = (const int*)d_in[0];
    const int*   observ  = (const int*)d_in[1];
    const float* aemb    = (const float*)d_in[2];
    const float* oemb    = (const float*)d_in[3];
    const float* temb    = (const float*)d_in[4];
    const float* Wq      = (const float*)d_in[5];
    const float* bq      = (const float*)d_in[6];
    const float* Wk      = (const float*)d_in[7];
    const float* bk      = (const float*)d_in[8];
    const float* Wv      = (const float*)d_in[9];
    const float* bv      = (const float*)d_in[10];
    const float* Wo      = (const float*)d_in[11];
    const float* bo      = (const float*)d_in[12];
    const float* ln1_g   = (const float*)d_in[13];
    const float* ln1_b   = (const float*)d_in[14];
    const float* ln2_g   = (const float*)d_in[15];
    const float* ln2_b   = (const float*)d_in[16];
    const float* W1      = (const float*)d_in[17];
    const float* b1      = (const float*)d_in[18];
    const float* W2      = (const float*)d_in[19];
    const float* b2      = (const float*)d_in[20];
    const float* out_g   = (const float*)d_in[21];
    const float* out_b   = (const float*)d_in[22];
    const float* Wout    = (const float*)d_in[23];
    const float* bout    = (const float*)d_in[24];

    float *x, *h, *q, *k, *v, *o, *ff, *S, *ct, *st;
    __nv_bfloat16 *ah, *al, *bh, *bl, *qh, *ql, *kh, *kl, *vh, *vl;
    cudaGetSymbolAddress((void**)&x,  g_x);
    cudaGetSymbolAddress((void**)&h,  g_h);
    cudaGetSymbolAddress((void**)&q,  g_q);
    cudaGetSymbolAddress((void**)&k,  g_k);
    cudaGetSymbolAddress((void**)&v,  g_v);
    cudaGetSymbolAddress((void**)&o,  g_o);
    cudaGetSymbolAddress((void**)&ff, g_ff);
    cudaGetSymbolAddress((void**)&S,  g_S);
    cudaGetSymbolAddress((void**)&ct, g_cos);
    cudaGetSymbolAddress((void**)&st, g_sin);
    cudaGetSymbolAddress((void**)&ah, g_ah);
    cudaGetSymbolAddress((void**)&al, g_al);
    cudaGetSymbolAddress((void**)&bh, g_bh);
    cudaGetSymbolAddress((void**)&bl, g_bl);
    cudaGetSymbolAddress((void**)&qh, g_qh);
    cudaGetSymbolAddress((void**)&ql, g_ql);
    cudaGetSymbolAddress((void**)&kh, g_kh);
    cudaGetSymbolAddress((void**)&kl, g_kl);
    cudaGetSymbolAddress((void**)&vh, g_vh);
    cudaGetSymbolAddress((void**)&vl, g_vl);

    static bool attn_cfg = false;
    if (!attn_cfg) {
        cudaFuncSetAttribute(attn_scores_mma, cudaFuncAttributeMaxDynamicSharedMemorySize, 4 * TBYTES);
        cudaFuncSetAttribute(attn_pv_mma,     cudaFuncAttributeMaxDynamicSharedMemorySize, PVSMEM);
        attn_cfg = true;
    }

    trig_kernel<<<(TT * 32 + 255) / 256, 256>>>(ct, st);
    embed_kernel<<<(BT * DD + 255) / 256, 256>>>(actions, observ, aemb, oemb, temb, x);

    for (int i = 0; i < LL; i++) {
        ln_kernel<<<BT, 256>>>(x, ln1_g + (size_t)i * DD, ln1_b + (size_t)i * DD, h);
        conv_A(h, ah, al, BT, DD);

        conv_B(Wq + (size_t)i * DD * DD, bh, bl, DD, DD);
        gemm<0>(ah, al, bh, bl, bq + (size_t)i * DD, nullptr, q, BT, DD, DD);
        conv_B(Wk + (size_t)i * DD * DD, bh, bl, DD, DD);
        gemm<0>(ah, al, bh, bl, bk + (size_t)i * DD, nullptr, k, BT, DD, DD);
        conv_B(Wv + (size_t)i * DD * DD, bh, bl, DD, DD);
        gemm<0>(ah, al, bh, bl, bv + (size_t)i * DD, nullptr, v, BT, DD, DD);

        rope_split_kernel<<<(BT * (DD / 2) + 255) / 256, 256>>>(q, k, ct, st, qh, ql, kh, kl);
        vsplit_kernel<<<dim3(TT / 32, DD / 32, BB), 256>>>(v, vh, vl);

        attn_scores_mma<<<dim3(TT / 128, TT / 128, BB * HH), 256, 4 * TBYTES>>>(qh, ql, kh, kl, S);
        softmax_kernel<<<dim3(TT, BB * HH), 256>>>(S);
        attn_pv_mma<<<dim3(TT / 128, BB * HH), 256, PVSMEM>>>(S, vh, vl, o);

        conv_A(o, ah, al, BT, DD);
        conv_B(Wo + (size_t)i * DD * DD, bh, bl, DD, DD);
        gemm<2>(ah, al, bh, bl, bo + (size_t)i * DD, x, x, BT, DD, DD);

        ln_kernel<<<BT, 256>>>(x, ln2_g + (size_t)i * DD, ln2_b + (size_t)i * DD, h);
        conv_A(h, ah, al, BT, DD);
        conv_B(W1 + (size_t)i * DD * DFF, bh, bl, DD, DFF);
        gemm<1>(ah, al, bh, bl, b1 + (size_t)i * DFF, nullptr, ff, BT, DFF, DD);

        conv_A(ff, ah, al, BT, DFF);
        conv_B(W2 + (size_t)i * DFF * DD, bh, bl, DFF, DD);
        gemm<2>(ah, al, bh, bl, b2 + (size_t)i * DD, x, x, BT, DD, DFF);
    }

    ln_kernel<<<BT, 256>>>(x, out_g, out_b, h);
    conv_A(h, ah, al, BT, DD);
    conv_B(Wout, bh, bl, DD, OV);
    gemm<0>(ah, al, bh, bl, bout, nullptr, (float*)d_out, BT, OV, DD);
}

// round 9
// speedup vs baseline: 4.1578x; 1.2791x over previous
#include <cuda_runtime.h>
#include <cuda_bf16.h>
#include <math.h>
#include <stdint.h>

#define LL 2
#define DD 1024
#define HH 16
#define DHH 64
#define DFF 4096
#define BB 2
#define TT 2048
#define OV 4096
#define BT (BB*TT)   // 4096

// ---------------- scratch (device globals; no runtime allocation) ----------------
__device__ float g_x [BT*DD];
__device__ float g_q [BT*DD];
__device__ float g_k [BT*DD];
__device__ float g_v [BT*DD];
__device__ float g_cos[TT*32];
__device__ float g_sin[TT*32];
// bf16 split operands (16B-aligned for vector access)
__device__ __align__(16) __nv_bfloat16 g_ah[(size_t)BT*DD];    // activation hi [BT,DD]
__device__ __align__(16) __nv_bfloat16 g_al[(size_t)BT*DD];
__device__ __align__(16) __nv_bfloat16 g_fh[(size_t)BT*DFF];   // ff hi [BT,DFF]
__device__ __align__(16) __nv_bfloat16 g_fl[(size_t)BT*DFF];
__device__ __align__(16) __nv_bfloat16 g_bh[(size_t)DFF*DD];   // B^T hi [N,K]
__device__ __align__(16) __nv_bfloat16 g_bl[(size_t)DFF*DD];
// attention split operands
__device__ __align__(16) __nv_bfloat16 g_qh[(size_t)BB*HH*TT*DHH];  // [bh][t][d]
__device__ __align__(16) __nv_bfloat16 g_ql[(size_t)BB*HH*TT*DHH];
__device__ __align__(16) __nv_bfloat16 g_kh[(size_t)BB*HH*TT*DHH];
__device__ __align__(16) __nv_bfloat16 g_kl[(size_t)BB*HH*TT*DHH];
__device__ __align__(16) __nv_bfloat16 g_vh[(size_t)BB*HH*DHH*TT];  // [bh][d][t]
__device__ __align__(16) __nv_bfloat16 g_vl[(size_t)BB*HH*DHH*TT];

// ---------------- warp-MMA primitives (baseline PTX; no sm_103a features) ----------
__device__ __forceinline__ uint32_t smem_u32(const void* p) {
    uint32_t a;
    asm("{ .reg .u64 t; cvta.to.shared.u64 t, %1; cvt.u32.u64 %0, t; }" : "=r"(a) : "l"(p));
    return a;
}
__device__ __forceinline__ void ldm4(uint32_t* r, uint32_t addr) {
    asm volatile("ldmatrix.sync.aligned.m8n8.x4.shared.b16 {%0,%1,%2,%3}, [%4];"
                 : "=r"(r[0]), "=r"(r[1]), "=r"(r[2]), "=r"(r[3]) : "r"(addr));
}
__device__ __forceinline__ void mma16816(float* d, const uint32_t* a, const uint32_t* b) {
    asm volatile("mma.sync.aligned.m16n8k16.row.col.f32.bf16.bf16.f32 "
                 "{%0,%1,%2,%3}, {%4,%5,%6,%7}, {%8,%9}, {%0,%1,%2,%3};"
                 : "+f"(d[0]), "+f"(d[1]), "+f"(d[2]), "+f"(d[3])
                 : "r"(a[0]), "r"(a[1]), "r"(a[2]), "r"(a[3]), "r"(b[0]), "r"(b[1]));
}
#define CPA(dst, src) asm volatile("cp.async.cg.shared.global [%0], [%1], 16;" :: "r"(dst), "l"(src))
#define CPC()         asm volatile("cp.async.commit_group;")
#define CPW(n)        asm volatile("cp.async.wait_group %0;" :: "n"(n))

__device__ __forceinline__ uint32_t bfpack(float x, float y) {
    __nv_bfloat162 t;
    t.x = __float2bfloat16_rn(x);
    t.y = __float2bfloat16_rn(y);
    return *(uint32_t*)&t;
}
// split one fp32 pair into hi pack + lo pack
__device__ __forceinline__ void bfsplit2(float x, float y, uint32_t& hi, uint32_t& lo) {
    __nv_bfloat16 hx = __float2bfloat16_rn(x), hy = __float2bfloat16_rn(y);
    __nv_bfloat162 H; H.x = hx; H.y = hy;
    hi = *(uint32_t*)&H;
    lo = bfpack(x - __bfloat162float(hx), y - __bfloat162float(hy));
}

// ---------------- split + transpose: W[K,N] -> Bt[N,K] hi/lo ----------------
__global__ void convT_kernel(const float* __restrict__ W, __nv_bfloat16* __restrict__ ht,
                             __nv_bfloat16* __restrict__ lt, int K, int N) {
    __shared__ float t[64][33];
    int n0 = blockIdx.x * 32, k0 = blockIdx.y * 64;
    int tx = threadIdx.x & 31, ty = threadIdx.x >> 5;
#pragma unroll
    for (int ky = 0; ky < 64; ky += 8)
        t[ky + ty][tx] = W[(size_t)(k0 + ky + ty) * N + n0 + tx];
    __syncthreads();
    int kl = threadIdx.x & 63, nb = threadIdx.x >> 6;
#pragma unroll
    for (int n = nb; n < 32; n += 4) {
        float v = t[kl][n];
        __nv_bfloat16 h = __float2bfloat16_rn(v);
        size_t o = (size_t)(n0 + n) * K + k0 + kl;
        ht[o] = h;
        lt[o] = __float2bfloat16_rn(v - __bfloat162float(h));
    }
}

// ---------------- HMMA split-bf16 GEMM, cp.async double-buffered ----------------
// EPI: 0 = bias -> fp32 C; 1 = bias+GELU -> split (Chi, Clo); 2 = bias+residual -> fp32 C
#define TROW 72
#define TBYTES (128*TROW*2)      // 18432 per tile
#define GSMEM (2*4*TBYTES)       // 147456

template <int EPI>
__global__ __launch_bounds__(256)
void gemm_mma(const __nv_bfloat16* __restrict__ Ahi, const __nv_bfloat16* __restrict__ Alo,
              const __nv_bfloat16* __restrict__ Bhi, const __nv_bfloat16* __restrict__ Blo,
              const float* __restrict__ bias, const float* __restrict__ R,
              float* __restrict__ C, __nv_bfloat16* __restrict__ Chi,
              __nv_bfloat16* __restrict__ Clo, int M, int N, int K) {
    extern __shared__ __align__(16) char smem[];
    const uint32_t sb = smem_u32(smem);
    int tid = threadIdx.x, lane = tid & 31, w = tid >> 5;
    int wm = w >> 2, wn = w & 3;
    int bm = blockIdx.y << 7, bn = blockIdx.x << 7;

    float acc[4][4][4];
#pragma unroll
    for (int i = 0; i < 4; i++)
#pragma unroll
        for (int j = 0; j < 4; j++)
#pragma unroll
            for (int z = 0; z < 4; z++) acc[i][j][z] = 0.f;

    int lrow = tid >> 3, lseg = tid & 7;
    auto issue = [&](int kc, int st) {
        int kb = kc << 6;
        uint32_t base = sb + st * 4 * TBYTES;
#pragma unroll
        for (int i = 0; i < 4; i++) {
            int row = lrow + i * 32;
            uint32_t so = base + (uint32_t)(row * 144 + lseg * 16);
            size_t ga = (size_t)(bm + row) * K + kb + lseg * 8;
            size_t gb = (size_t)(bn + row) * K + kb + lseg * 8;
            CPA(so,              Ahi + ga);
            CPA(so + TBYTES,     Alo + ga);
            CPA(so + 2*TBYTES,   Bhi + gb);
            CPA(so + 3*TBYTES,   Blo + gb);
        }
        CPC();
    };

    const int nch = K >> 6;
    issue(0, 0);

    int a_row = wm * 64 + (lane & 15), a_col = (lane >> 4) << 3;
    int b_row = wn * 32 + ((lane >> 4) << 3) + (lane & 7), b_col = ((lane >> 3) & 1) << 3;
    uint32_t aoff = (uint32_t)(a_row * TROW + a_col) * 2;
    uint32_t boff = (uint32_t)(b_row * TROW + b_col) * 2 + 2 * TBYTES;

    for (int kc = 0; kc < nch; kc++) {
        if (kc + 1 < nch) { issue(kc + 1, (kc + 1) & 1); CPW(1); }
        else              { CPW(0); }
        __syncthreads();
        uint32_t base = sb + (kc & 1) * 4 * TBYTES;
        uint32_t aoff_h = base + aoff, aoff_l = aoff_h + TBYTES;
        uint32_t boff_h = base + boff, boff_l = boff_h + TBYTES;
#pragma unroll
        for (int ks = 0; ks < 4; ks++) {
            uint32_t ah[4][4], al[4][4], bh[8], bl[8];
            uint32_t kso = (uint32_t)(ks * 32);
#pragma unroll
            for (int mi = 0; mi < 4; mi++) {
                ldm4(ah[mi], aoff_h + (uint32_t)(mi * 16 * TROW * 2) + kso);
                ldm4(al[mi], aoff_l + (uint32_t)(mi * 16 * TROW * 2) + kso);
            }
            ldm4(&bh[0], boff_h + kso);
            ldm4(&bh[4], boff_h + (uint32_t)(16 * TROW * 2) + kso);
#pragma unroll
            for (int mi = 0; mi < 4; mi++)
#pragma unroll
                for (int ni = 0; ni < 4; ni++)
                    mma16816(acc[mi][ni], ah[mi], &bh[ni * 2]);
#pragma unroll
            for (int mi = 0; mi < 4; mi++)
#pragma unroll
                for (int ni = 0; ni < 4; ni++)
                    mma16816(acc[mi][ni], al[mi], &bh[ni * 2]);
            ldm4(&bl[0], boff_l + kso);
            ldm4(&bl[4], boff_l + (uint32_t)(16 * TROW * 2) + kso);
#pragma unroll
            for (int mi = 0; mi < 4; mi++)
#pragma unroll
                for (int ni = 0; ni < 4; ni++)
                    mma16816(acc[mi][ni], ah[mi], &bl[ni * 2]);
        }
        __syncthreads();
    }

    // ---- epilogue ----
#pragma unroll
    for (int mi = 0; mi < 4; mi++) {
#pragma unroll
        for (int ni = 0; ni < 4; ni++) {
            int r0 = bm + wm * 64 + mi * 16 + (lane >> 2);
            int c0 = bn + wn * 32 + ni * 8 + ((lane & 3) << 1);
#pragma unroll
            for (int half = 0; half < 2; half++) {
                int gm = r0 + half * 8;
                float v0 = acc[mi][ni][half * 2]     + bias[c0];
                float v1 = acc[mi][ni][half * 2 + 1] + bias[c0 + 1];
                if (EPI == 1) {
                    v0 *= normcdff(v0); v1 *= normcdff(v1);
                    uint32_t hi, lo;
                    bfsplit2(v0, v1, hi, lo);
                    *(uint32_t*)&Chi[(size_t)gm * N + c0] = hi;
                    *(uint32_t*)&Clo[(size_t)gm * N + c0] = lo;
                } else {
                    if (EPI == 2) {
                        v0 += R[(size_t)gm * N + c0];
                        v1 += R[(size_t)gm * N + c0 + 1];
                    }
                    float2 o; o.x = v0; o.y = v1;
                    *(float2*)&C[(size_t)gm * N + c0] = o;
                }
            }
        }
    }
}

// ---------------- RoPE trig tables (double precision; fast-math-proof) ----------------
__global__ void trig_kernel(float* __restrict__ ct, float* __restrict__ st) {
    int i = blockIdx.x * 256 + threadIdx.x;
    if (i >= TT * 32) return;
    int t = i >> 5, p = i & 31;
    double inv = exp2(-13.287712379549449 * ((double)(2 * p) * (1.0 / 64.0)));
    float invf = (float)inv;
    float angf = (float)((double)t * (double)invf);
    double c, s;
    sincos((double)angf, &s, &c);
    ct[i] = (float)c;
    st[i] = (float)s;
}

// ---------------- embedding ----------------
__global__ void embed_kernel(const int* __restrict__ act, const int* __restrict__ obs,
                             const float* __restrict__ aemb, const float* __restrict__ oemb,
                             const float* __restrict__ temb, float* __restrict__ x) {
    int idx = blockIdx.x * blockDim.x + threadIdx.x;
    if (idx >= BT * DD) return;
    int r = idx / DD, d = idx % DD;
    x[idx] = aemb[(size_t)act[r] * DD + d] + temb[d]
           + oemb[(size_t)obs[r] * DD + d] + temb[DD + d];
}

// ---------------- layernorm -> split bf16 hi/lo directly ----------------
__global__ void ln_kernel(const float* __restrict__ x, const float* __restrict__ g,
                          const float* __restrict__ b, __nv_bfloat16* __restrict__ yh,
                          __nv_bfloat16* __restrict__ yl) {
    int r = blockIdx.x;
    const float* xr = x + (size_t)r * DD;
    float v[4];
    float s = 0.f, ss = 0.f;
#pragma unroll
    for (int i = 0; i < 4; i++) {
        float t = xr[threadIdx.x + i * 256];
        v[i] = t; s += t; ss += t * t;
    }
#pragma unroll
    for (int o = 16; o > 0; o >>= 1) {
        s  += __shfl_xor_sync(0xffffffffu, s,  o);
        ss += __shfl_xor_sync(0xffffffffu, ss, o);
    }
    __shared__ float rs[8], rss[8];
    int w = threadIdx.x >> 5;
    if ((threadIdx.x & 31) == 0) { rs[w] = s; rss[w] = ss; }
    __syncthreads();
    if (threadIdx.x == 0) {
        float a = 0.f, c = 0.f;
#pragma unroll
        for (int i = 0; i < 8; i++) { a += rs[i]; c += rss[i]; }
        rs[0] = a; rss[0] = c;
    }
    __syncthreads();
    float mean = rs[0] * (1.f / DD);
    float var  = rss[0] * (1.f / DD) - mean * mean;
    float inv  = rsqrtf(var + 1e-5f);
#pragma unroll
    for (int i = 0; i < 4; i++) {
        int d = threadIdx.x + i * 256;
        float val = (v[i] - mean) * inv * g[d] + b[d];
        __nv_bfloat16 h = __float2bfloat16_rn(val);
        yh[(size_t)r * DD + d] = h;
        yl[(size_t)r * DD + d] = __float2bfloat16_rn(val - __bfloat162float(h));
    }
}

// ---------------- RoPE + hi/lo split into per-head layout [bh][t][64] ----------------
__global__ void rope_split_kernel(const float* __restrict__ Q, const float* __restrict__ K,
                                  const float* __restrict__ ct, const float* __restrict__ st,
                                  __nv_bfloat16* __restrict__ qh, __nv_bfloat16* __restrict__ ql,
                                  __nv_bfloat16* __restrict__ kh, __nv_bfloat16* __restrict__ kl) {
    int idx = blockIdx.x * 256 + threadIdx.x;
    if (idx >= BT * (DD / 2)) return;
    int r  = idx >> 9;
    int c2 = idx & 511;
    int hh = c2 >> 5, p = c2 & 31;
    int b = r >> 11, t = r & (TT - 1);
    float c = ct[t * 32 + p];
    float s = st[t * 32 + p];
    size_t ib = (size_t)r * DD + hh * 64 + 2 * p;
    size_t ob = ((size_t)(b * HH + hh) * TT + t) * 64 + 2 * p;

    float q0 = Q[ib], q1 = Q[ib + 1];
    float o0 = q0 * c - q1 * s, o1 = q0 * s + q1 * c;
    __nv_bfloat16 h0 = __float2bfloat16_rn(o0), h1 = __float2bfloat16_rn(o1);
    qh[ob] = h0; qh[ob + 1] = h1;
    ql[ob]     = __float2bfloat16_rn(o0 - __bfloat162float(h0));
    ql[ob + 1] = __float2bfloat16_rn(o1 - __bfloat162float(h1));

    float k0 = K[ib], k1 = K[ib + 1];
    float e0 = k0 * c - k1 * s, e1 = k0 * s + k1 * c;
    __nv_bfloat16 g0 = __float2bfloat16_rn(e0), g1 = __float2bfloat16_rn(e1);
    kh[ob] = g0; kh[ob + 1] = g1;
    kl[ob]     = __float2bfloat16_rn(e0 - __bfloat162float(g0));
    kl[ob + 1] = __float2bfloat16_rn(e1 - __bfloat162float(g1));
}

// ---------------- V split + transpose into [bh][d][t] ----------------
__global__ void vsplit_kernel(const float* __restrict__ V,
                              __nv_bfloat16* __restrict__ vh, __nv_bfloat16* __restrict__ vl) {
    __shared__ float ts[32][33];
    int t0 = blockIdx.x * 32, d0 = blockIdx.y * 32, b = blockIdx.z;
    int tx = threadIdx.x & 31, ty = threadIdx.x >> 5;
#pragma unroll
    for (int i = ty; i < 32; i += 8)
        ts[i][tx] = V[((size_t)b * TT + t0 + i) * DD + d0 + tx];
    __syncthreads();
    int hh = d0 >> 6, dl0 = d0 & 63;
#pragma unroll
    for (int i = ty; i < 32; i += 8) {
        float v = ts[tx][i];
        size_t o = ((size_t)(b * HH + hh) * 64 + dl0 + i) * TT + t0 + tx;
        __nv_bfloat16 h = __float2bfloat16_rn(v);
        vh[o] = h;
        vl[o] = __float2bfloat16_rn(v - __bfloat162float(h));
    }
}

// ================= fused flash attention =================
// one CTA per (q-tile 128, bh); 8 warps, each owns 16 q-rows x all 128 k-cols.
// K/V double-buffered cp.async; P kept in registers (FA-2 frag reinterpret);
// output written as hi/lo bf16 split, row-major [BT][DD].
#define FQ_H 0
#define FQ_L 18432
#define FK_H(st) (36864 + (st)*36864)
#define FK_L(st) (FK_H(st) + 18432)
#define FV_H(st) (110592 + (st)*34816)
#define FV_L(st) (FV_H(st) + 17408)
#define FSMEM 180224

__global__ __launch_bounds__(256)
void flash_attn(const __nv_bfloat16* __restrict__ Qh, const __nv_bfloat16* __restrict__ Ql,
                const __nv_bfloat16* __restrict__ Kh, const __nv_bfloat16* __restrict__ Kl,
                const __nv_bfloat16* __restrict__ Vh, const __nv_bfloat16* __restrict__ Vl,
                __nv_bfloat16* __restrict__ Oh, __nv_bfloat16* __restrict__ Ol) {
    int qt = gridDim.x - 1 - blockIdx.x;     // largest work first
    int bh = blockIdx.y;
    int b = bh >> 4, hh = bh & 15;
    extern __shared__ __align__(16) char smem[];
    const uint32_t sb = smem_u32(smem);
    int tid = threadIdx.x, lane = tid & 31, w = tid >> 5;

    // ---- stage Q tile (plain stores; each warp writes its own rows) ----
    {
        int row = tid >> 1, segb = (tid & 1) * 4;
        size_t qg = ((size_t)bh * TT + qt * 128 + row) * 64 + segb * 8;
#pragma unroll
        for (int s = 0; s < 4; s++) {
            uint32_t so = (uint32_t)(row * 144 + (segb + s) * 16);
            *(uint4*)(smem + FQ_H + so) = *(const uint4*)(Qh + qg + s * 8);
            *(uint4*)(smem + FQ_L + so) = *(const uint4*)(Ql + qg + s * 8);
        }
    }

    auto issueKV = [&](int kt, int st) {
        int row = tid >> 1, segb = (tid & 1) * 4;
        size_t kg = ((size_t)bh * TT + kt * 128 + row) * 64 + segb * 8;
#pragma unroll
        for (int s = 0; s < 4; s++) {
            uint32_t so = (uint32_t)(row * 144 + (segb + s) * 16);
            CPA(sb + FK_H(st) + so, Kh + kg + s * 8);
            CPA(sb + FK_L(st) + so, Kl + kg + s * 8);
        }
        int vrow = tid >> 2, vsegb = (tid & 3) * 4;
        size_t vg = ((size_t)bh * 64 + vrow) * TT + kt * 128 + vsegb * 8;
#pragma unroll
        for (int s = 0; s < 4; s++) {
            uint32_t so = (uint32_t)(vrow * 272 + (vsegb + s) * 16);
            CPA(sb + FV_H(st) + so, Vh + vg + s * 8);
            CPA(sb + FV_L(st) + so, Vl + vg + s * 8);
        }
        CPC();
    };
    issueKV(0, 0);
    __syncthreads();

    // ---- Q fragments (persist in registers) ----
    uint32_t qfh[4][4], qfl[4][4];
    {
        int a_row = w * 16 + (lane & 15), a_col = (lane >> 4) << 3;
        uint32_t qa = (uint32_t)(a_row * 144 + a_col * 2);
#pragma unroll
        for (int ks = 0; ks < 4; ks++) {
            ldm4(qfh[ks], sb + FQ_H + qa + ks * 32);
            ldm4(qfl[ks], sb + FQ_L + qa + ks * 32);
        }
    }

    float m0 = -3.0e38f, m1 = -3.0e38f, l0 = 0.f, l1 = 0.f;
    float O[8][4];
#pragma unroll
    for (int i = 0; i < 8; i++)
#pragma unroll
        for (int z = 0; z < 4; z++) O[i][z] = 0.f;

    int b_rowi = ((lane >> 4) << 3) + (lane & 7);
    int b_colb = (((lane >> 3) & 1) << 3) * 2;   // bytes

    for (int kt = 0; kt <= qt; kt++) {
        if (kt < qt) { issueKV(kt + 1, (kt + 1) & 1); CPW(1); }
        else         { CPW(0); }
        __syncthreads();
        uint32_t kb_h = sb + FK_H(kt & 1), kb_l = sb + FK_L(kt & 1);
        uint32_t vb_h = sb + FV_H(kt & 1), vb_l = sb + FV_L(kt & 1);

        // ---- scores P[16 x 128] = (Qh+Ql)Kh + Qh Kl ----
        float P[16][4];
#pragma unroll
        for (int i = 0; i < 16; i++)
#pragma unroll
            for (int z = 0; z < 4; z++) P[i][z] = 0.f;
#pragma unroll
        for (int ks = 0; ks < 4; ks++) {
            uint32_t kso = (uint32_t)(ks * 32);
#pragma unroll
            for (int nb = 0; nb < 8; nb++) {
                uint32_t addr = (uint32_t)((nb * 16 + b_rowi) * 144) + b_colb + kso;
                uint32_t kf[4], kfl[4];
                ldm4(kf, kb_h + addr);
                mma16816(P[2*nb],   qfh[ks], &kf[0]);
                mma16816(P[2*nb+1], qfh[ks], &kf[2]);
                mma16816(P[2*nb],   qfl[ks], &kf[0]);
                mma16816(P[2*nb+1], qfl[ks], &kf[2]);
                ldm4(kfl, kb_l + addr);
                mma16816(P[2*nb],   qfh[ks], &kfl[0]);
                mma16816(P[2*nb+1], qfh[ks], &kfl[2]);
            }
        }
        // scale + causal mask (diagonal tile only)
#pragma unroll
        for (int i = 0; i < 16; i++)
#pragma unroll
            for (int z = 0; z < 4; z++) P[i][z] *= 0.125f;
        if (kt == qt) {
            int r0 = w * 16 + (lane >> 2);
#pragma unroll
            for (int i = 0; i < 16; i++) {
#pragma unroll
                for (int z = 0; z < 4; z++) {
                    int col = i * 8 + ((lane & 3) << 1) + (z & 1);
                    int row = r0 + ((z >> 1) << 3);
                    if (col > row) P[i][z] = -3.0e38f;
                }
            }
        }
        // ---- online softmax (stats local to 4-lane quad) ----
        float mx0 = -3.0e38f, mx1 = -3.0e38f;
#pragma unroll
        for (int i = 0; i < 16; i++) {
            mx0 = fmaxf(mx0, fmaxf(P[i][0], P[i][1]));
            mx1 = fmaxf(mx1, fmaxf(P[i][2], P[i][3]));
        }
        mx0 = fmaxf(mx0, __shfl_xor_sync(0xffffffffu, mx0, 1));
        mx0 = fmaxf(mx0, __shfl_xor_sync(0xffffffffu, mx0, 2));
        mx1 = fmaxf(mx1, __shfl_xor_sync(0xffffffffu, mx1, 1));
        mx1 = fmaxf(mx1, __shfl_xor_sync(0xffffffffu, mx1, 2));
        float mn0 = fmaxf(m0, mx0), mn1 = fmaxf(m1, mx1);
        float al0 = expf(m0 - mn0), al1 = expf(m1 - mn1);
        m0 = mn0; m1 = mn1;
        float s0 = 0.f, s1 = 0.f;
#pragma unroll
        for (int i = 0; i < 16; i++) {
            P[i][0] = expf(P[i][0] - m0); s0 += P[i][0];
            P[i][1] = expf(P[i][1] - m0); s0 += P[i][1];
            P[i][2] = expf(P[i][2] - m1); s1 += P[i][2];
            P[i][3] = expf(P[i][3] - m1); s1 += P[i][3];
        }
        s0 += __shfl_xor_sync(0xffffffffu, s0, 1);
        s0 += __shfl_xor_sync(0xffffffffu, s0, 2);
        s1 += __shfl_xor_sync(0xffffffffu, s1, 1);
        s1 += __shfl_xor_sync(0xffffffffu, s1, 2);
        l0 = l0 * al0 + s0;
        l1 = l1 * al1 + s1;
#pragma unroll
        for (int i = 0; i < 8; i++) {
            O[i][0] *= al0; O[i][1] *= al0;
            O[i][2] *= al1; O[i][3] *= al1;
        }
        // ---- PV: O += (Ph+Pl)Vh + Ph Vl ; P a-frags from accum regs ----
#pragma unroll
        for (int ks = 0; ks < 8; ks++) {
            uint32_t pah[4], pal[4];
            bfsplit2(P[2*ks][0],   P[2*ks][1],   pah[0], pal[0]);
            bfsplit2(P[2*ks][2],   P[2*ks][3],   pah[1], pal[1]);
            bfsplit2(P[2*ks+1][0], P[2*ks+1][1], pah[2], pal[2]);
            bfsplit2(P[2*ks+1][2], P[2*ks+1][3], pah[3], pal[3]);
            uint32_t kso = (uint32_t)(ks * 32);
#pragma unroll
            for (int nb = 0; nb < 4; nb++) {
                uint32_t addr = (uint32_t)((nb * 16 + b_rowi) * 272) + b_colb + kso;
                uint32_t vf[4], vfl[4];
                ldm4(vf, vb_h + addr);
                mma16816(O[2*nb],   pah, &vf[0]);
                mma16816(O[2*nb+1], pah, &vf[2]);
                mma16816(O[2*nb],   pal, &vf[0]);
                mma16816(O[2*nb+1], pal, &vf[2]);
                ldm4(vfl, vb_l + addr);
                mma16816(O[2*nb],   pah, &vfl[0]);
                mma16816(O[2*nb+1], pah, &vfl[2]);
            }
        }
        __syncthreads();
    }

    // ---- epilogue: normalize, split hi/lo, store row-major [BT][DD] ----
    float i0 = 1.f / l0, i1 = 1.f / l1;
    int r0 = qt * 128 + w * 16 + (lane >> 2);
    int c0 = hh * 64 + ((lane & 3) << 1);
#pragma unroll
    for (int nj = 0; nj < 8; nj++) {
        int cc = c0 + nj * 8;
        uint32_t hi, lo;
        bfsplit2(O[nj][0] * i0, O[nj][1] * i0, hi, lo);
        size_t o0 = ((size_t)b * TT + r0) * DD + cc;
        *(uint32_t*)&Oh[o0] = hi;
        *(uint32_t*)&Ol[o0] = lo;
        bfsplit2(O[nj][2] * i1, O[nj][3] * i1, hi, lo);
        size_t o1 = ((size_t)b * TT + r0 + 8) * DD + cc;
        *(uint32_t*)&Oh[o1] = hi;
        *(uint32_t*)&Ol[o1] = lo;
    }
}

// ---------------- host-side helpers ----------------
static void conv_B(const float* W, __nv_bfloat16* bh, __nv_bfloat16* bl, int K, int N) {
    convT_kernel<<<dim3(N / 32, K / 64), 256>>>(W, bh, bl, K, N);
}
template <int EPI>
static void gemm(const __nv_bfloat16* ah, const __nv_bfloat16* al,
                 const __nv_bfloat16* bh, const __nv_bfloat16* bl,
                 const float* bias, const float* R, float* C,
                 __nv_bfloat16* Chi, __nv_bfloat16* Clo, int M, int N, int K) {
    static bool cfg = false;
    if (!cfg) {
        cudaFuncSetAttribute(gemm_mma<EPI>, cudaFuncAttributeMaxDynamicSharedMemorySize, GSMEM);
        cfg = true;
    }
    gemm_mma<EPI><<<dim3(N / 128, M / 128), 256, GSMEM>>>(ah, al, bh, bl, bias, R, C, Chi, Clo, M, N, K);
}

// ---------------- launch sequence ----------------
extern "C" void kernel_launch(void* const* d_in, const int* in_sizes, int n_in,
                              void* d_out, int out_size) {
    const int*   actions = (const int*)d_in[0];
    const int*   observ  = (const int*)d_in[1];
    const float* aemb    = (const float*)d_in[2];
    const float* oemb    = (const float*)d_in[3];
    const float* temb    = (const float*)d_in[4];
    const float* Wq      = (const float*)d_in[5];
    const float* bq      = (const float*)d_in[6];
    const float* Wk      = (const float*)d_in[7];
    const float* bk      = (const float*)d_in[8];
    const float* Wv      = (const float*)d_in[9];
    const float* bv      = (const float*)d_in[10];
    const float* Wo      = (const float*)d_in[11];
    const float* bo      = (const float*)d_in[12];
    const float* ln1_g   = (const float*)d_in[13];
    const float* ln1_b   = (const float*)d_in[14];
    const float* ln2_g   = (const float*)d_in[15];
    const float* ln2_b   = (const float*)d_in[16];
    const float* W1      = (const float*)d_in[17];
    const float* b1      = (const float*)d_in[18];
    const float* W2      = (const float*)d_in[19];
    const float* b2      = (const float*)d_in[20];
    const float* out_g   = (const float*)d_in[21];
    const float* out_b   = (const float*)d_in[22];
    const float* Wout    = (const float*)d_in[23];
    const float* bout    = (const float*)d_in[24];

    float *x, *q, *k, *v, *ct, *st;
    __nv_bfloat16 *ah, *al, *fh, *fl, *bh, *bl, *qh, *ql, *kh, *kl, *vh, *vl;
    cudaGetSymbolAddress((void**)&x,  g_x);
    cudaGetSymbolAddress((void**)&q,  g_q);
    cudaGetSymbolAddress((void**)&k,  g_k);
    cudaGetSymbolAddress((void**)&v,  g_v);
    cudaGetSymbolAddress((void**)&ct, g_cos);
    cudaGetSymbolAddress((void**)&st, g_sin);
    cudaGetSymbolAddress((void**)&ah, g_ah);
    cudaGetSymbolAddress((void**)&al, g_al);
    cudaGetSymbolAddress((void**)&fh, g_fh);
    cudaGetSymbolAddress((void**)&fl, g_fl);
    cudaGetSymbolAddress((void**)&bh, g_bh);
    cudaGetSymbolAddress((void**)&bl, g_bl);
    cudaGetSymbolAddress((void**)&qh, g_qh);
    cudaGetSymbolAddress((void**)&ql, g_ql);
    cudaGetSymbolAddress((void**)&kh, g_kh);
    cudaGetSymbolAddress((void**)&kl, g_kl);
    cudaGetSymbolAddress((void**)&vh, g_vh);
    cudaGetSymbolAddress((void**)&vl, g_vl);

    static bool fcfg = false;
    if (!fcfg) {
        cudaFuncSetAttribute(flash_attn, cudaFuncAttributeMaxDynamicSharedMemorySize, FSMEM);
        fcfg = true;
    }

    trig_kernel<<<(TT * 32 + 255) / 256, 256>>>(ct, st);
    embed_kernel<<<(BT * DD + 255) / 256, 256>>>(actions, observ, aemb, oemb, temb, x);

    for (int i = 0; i < LL; i++) {
        ln_kernel<<<BT, 256>>>(x, ln1_g + (size_t)i * DD, ln1_b + (size_t)i * DD, ah, al);

        conv_B(Wq + (size_t)i * DD * DD, bh, bl, DD, DD);
        gemm<0>(ah, al, bh, bl, bq + (size_t)i * DD, nullptr, q, nullptr, nullptr, BT, DD, DD);
        conv_B(Wk + (size_t)i * DD * DD, bh, bl, DD, DD);
        gemm<0>(ah, al, bh, bl, bk + (size_t)i * DD, nullptr, k, nullptr, nullptr, BT, DD, DD);
        conv_B(Wv + (size_t)i * DD * DD, bh, bl, DD, DD);
        gemm<0>(ah, al, bh, bl, bv + (size_t)i * DD, nullptr, v, nullptr, nullptr, BT, DD, DD);

        rope_split_kernel<<<(BT * (DD / 2) + 255) / 256, 256>>>(q, k, ct, st, qh, ql, kh, kl);
        vsplit_kernel<<<dim3(TT / 32, DD / 32, BB), 256>>>(v, vh, vl);

        flash_attn<<<dim3(TT / 128, BB * HH), 256, FSMEM>>>(qh, ql, kh, kl, vh, vl, ah, al);

        conv_B(Wo + (size_t)i * DD * DD, bh, bl, DD, DD);
        gemm<2>(ah, al, bh, bl, bo + (size_t)i * DD, x, x, nullptr, nullptr, BT, DD, DD);

        ln_kernel<<<BT, 256>>>(x, ln2_g + (size_t)i * DD, ln2_b + (size_t)i * DD, ah, al);
        conv_B(W1 + (size_t)i * DD * DFF, bh, bl, DD, DFF);
        gemm<1>(ah, al, bh, bl, b1 + (size_t)i * DFF, nullptr, nullptr, fh, fl, BT, DFF, DD);

        conv_B(W2 + (size_t)i * DFF * DD, bh, bl, DFF, DD);
        gemm<2>(fh, fl, bh, bl, b2 + (size_t)i * DD, x, x, nullptr, nullptr, BT, DD, DFF);
    }

    ln_kernel<<<BT, 256>>>(x, out_g, out_b, ah, al);
    conv_B(Wout, bh, bl, DD, OV);
    gemm<0>(ah, al, bh, bl, bout, nullptr, (float*)d_out, nullptr, nullptr, BT, OV, DD);
}

// round 10
// speedup vs baseline: 4.1787x; 1.0050x over previous
#include <cuda_runtime.h>
#include <cuda_bf16.h>
#include <math.h>
#include <stdint.h>

#define LL 2
#define DD 1024
#define HH 16
#define DHH 64
#define DFF 4096
#define BB 2
#define TT 2048
#define OV 4096
#define BT (BB*TT)   // 4096

// ---------------- scratch (device globals; no runtime allocation) ----------------
__device__ float g_x [BT*DD];
__device__ float g_q [BT*DD];
__device__ float g_k [BT*DD];
__device__ float g_v [BT*DD];
__device__ float g_cos[TT*32];
__device__ float g_sin[TT*32];
// bf16 split operands (16B-aligned for vector access)
__device__ __align__(16) __nv_bfloat16 g_ah[(size_t)BT*DD];    // activation hi [BT,DD]
__device__ __align__(16) __nv_bfloat16 g_al[(size_t)BT*DD];
__device__ __align__(16) __nv_bfloat16 g_fh[(size_t)BT*DFF];   // ff hi [BT,DFF]
__device__ __align__(16) __nv_bfloat16 g_fl[(size_t)BT*DFF];
__device__ __align__(16) __nv_bfloat16 g_bh[(size_t)DFF*DD];   // B^T hi [N,K]
__device__ __align__(16) __nv_bfloat16 g_bl[(size_t)DFF*DD];
// attention split operands
__device__ __align__(16) __nv_bfloat16 g_qh[(size_t)BB*HH*TT*DHH];  // [bh][t][d]
__device__ __align__(16) __nv_bfloat16 g_ql[(size_t)BB*HH*TT*DHH];
__device__ __align__(16) __nv_bfloat16 g_kh[(size_t)BB*HH*TT*DHH];
__device__ __align__(16) __nv_bfloat16 g_kl[(size_t)BB*HH*TT*DHH];
__device__ __align__(16) __nv_bfloat16 g_vh[(size_t)BB*HH*DHH*TT];  // [bh][d][t]
__device__ __align__(16) __nv_bfloat16 g_vl[(size_t)BB*HH*DHH*TT];

// ---------------- warp-MMA primitives (baseline PTX; no sm_103a features) ----------
__device__ __forceinline__ uint32_t smem_u32(const void* p) {
    uint32_t a;
    asm("{ .reg .u64 t; cvta.to.shared.u64 t, %1; cvt.u32.u64 %0, t; }" : "=r"(a) : "l"(p));
    return a;
}
__device__ __forceinline__ void ldm4(uint32_t* r, uint32_t addr) {
    asm volatile("ldmatrix.sync.aligned.m8n8.x4.shared.b16 {%0,%1,%2,%3}, [%4];"
                 : "=r"(r[0]), "=r"(r[1]), "=r"(r[2]), "=r"(r[3]) : "r"(addr));
}
__device__ __forceinline__ void mma16816(float* d, const uint32_t* a, const uint32_t* b) {
    asm volatile("mma.sync.aligned.m16n8k16.row.col.f32.bf16.bf16.f32 "
                 "{%0,%1,%2,%3}, {%4,%5,%6,%7}, {%8,%9}, {%0,%1,%2,%3};"
                 : "+f"(d[0]), "+f"(d[1]), "+f"(d[2]), "+f"(d[3])
                 : "r"(a[0]), "r"(a[1]), "r"(a[2]), "r"(a[3]), "r"(b[0]), "r"(b[1]));
}
#define CPA(dst, src) asm volatile("cp.async.cg.shared.global [%0], [%1], 16;" :: "r"(dst), "l"(src))
#define CPC()         asm volatile("cp.async.commit_group;")
#define CPW(n)        asm volatile("cp.async.wait_group %0;" :: "n"(n))

__device__ __forceinline__ uint32_t bfpack(float x, float y) {
    __nv_bfloat162 t;
    t.x = __float2bfloat16_rn(x);
    t.y = __float2bfloat16_rn(y);
    return *(uint32_t*)&t;
}
// split one fp32 pair into hi pack + lo pack
__device__ __forceinline__ void bfsplit2(float x, float y, uint32_t& hi, uint32_t& lo) {
    __nv_bfloat16 hx = __float2bfloat16_rn(x), hy = __float2bfloat16_rn(y);
    __nv_bfloat162 H; H.x = hx; H.y = hy;
    hi = *(uint32_t*)&H;
    lo = bfpack(x - __bfloat162float(hx), y - __bfloat162float(hy));
}

// ---------------- split + transpose: W[K,N] -> Bt[N,K] hi/lo ----------------
__global__ void convT_kernel(const float* __restrict__ W, __nv_bfloat16* __restrict__ ht,
                             __nv_bfloat16* __restrict__ lt, int K, int N) {
    __shared__ float t[64][33];
    int n0 = blockIdx.x * 32, k0 = blockIdx.y * 64;
    int tx = threadIdx.x & 31, ty = threadIdx.x >> 5;
#pragma unroll
    for (int ky = 0; ky < 64; ky += 8)
        t[ky + ty][tx] = W[(size_t)(k0 + ky + ty) * N + n0 + tx];
    __syncthreads();
    int kl = threadIdx.x & 63, nb = threadIdx.x >> 6;
#pragma unroll
    for (int n = nb; n < 32; n += 4) {
        float v = t[kl][n];
        __nv_bfloat16 h = __float2bfloat16_rn(v);
        size_t o = (size_t)(n0 + n) * K + k0 + kl;
        ht[o] = h;
        lt[o] = __float2bfloat16_rn(v - __bfloat162float(h));
    }
}

// ---------------- HMMA split-bf16 GEMM, cp.async 3-stage pipelined ----------------
// EPI: 0 = bias -> fp32 C; 1 = bias+GELU -> split (Chi, Clo); 2 = bias+residual -> fp32 C
#define TROW 72
#define TBYTES (128*TROW*2)      // 18432 per tile
#define GSMEM (3*4*TBYTES)       // 221184 (3 stages x 4 tiles)

template <int EPI>
__global__ __launch_bounds__(256)
void gemm_mma(const __nv_bfloat16* __restrict__ Ahi, const __nv_bfloat16* __restrict__ Alo,
              const __nv_bfloat16* __restrict__ Bhi, const __nv_bfloat16* __restrict__ Blo,
              const float* __restrict__ bias, const float* __restrict__ R,
              float* __restrict__ C, __nv_bfloat16* __restrict__ Chi,
              __nv_bfloat16* __restrict__ Clo, int M, int N, int K) {
    extern __shared__ __align__(16) char smem[];
    const uint32_t sb = smem_u32(smem);
    int tid = threadIdx.x, lane = tid & 31, w = tid >> 5;
    int wm = w >> 2, wn = w & 3;
    int bm = blockIdx.y << 7, bn = blockIdx.x << 7;

    float acc[4][4][4];
#pragma unroll
    for (int i = 0; i < 4; i++)
#pragma unroll
        for (int j = 0; j < 4; j++)
#pragma unroll
            for (int z = 0; z < 4; z++) acc[i][j][z] = 0.f;

    int lrow = tid >> 3, lseg = tid & 7;
    auto issue = [&](int kc, int st) {
        int kb = kc << 6;
        uint32_t base = sb + st * 4 * TBYTES;
#pragma unroll
        for (int i = 0; i < 4; i++) {
            int row = lrow + i * 32;
            uint32_t so = base + (uint32_t)(row * 144 + lseg * 16);
            size_t ga = (size_t)(bm + row) * K + kb + lseg * 8;
            size_t gb = (size_t)(bn + row) * K + kb + lseg * 8;
            CPA(so,              Ahi + ga);
            CPA(so + TBYTES,     Alo + ga);
            CPA(so + 2*TBYTES,   Bhi + gb);
            CPA(so + 3*TBYTES,   Blo + gb);
        }
        CPC();
    };

    const int nch = K >> 6;
    issue(0, 0);
    issue(1, 1);

    int a_row = wm * 64 + (lane & 15), a_col = (lane >> 4) << 3;
    int b_row = wn * 32 + ((lane >> 4) << 3) + (lane & 7), b_col = ((lane >> 3) & 1) << 3;
    uint32_t aoff = (uint32_t)(a_row * TROW + a_col) * 2;
    uint32_t boff = (uint32_t)(b_row * TROW + b_col) * 2 + 2 * TBYTES;

    for (int kc = 0; kc < nch; kc++) {
        if (kc + 1 < nch) { CPW(1); }    // chunk kc landed (kc+1 may still fly)
        else              { CPW(0); }    // last chunk: drain all
        __syncthreads();                 // one barrier per chunk; also protects stage reuse
        if (kc + 2 < nch) issue(kc + 2, (kc + 2) % 3);

        uint32_t base = sb + (uint32_t)((kc % 3) * 4 * TBYTES);
        uint32_t aoff_h = base + aoff, aoff_l = aoff_h + TBYTES;
        uint32_t boff_h = base + boff, boff_l = boff_h + TBYTES;
#pragma unroll
        for (int ks = 0; ks < 4; ks++) {
            uint32_t ah[4][4], al[4][4], bh[8], bl[8];
            uint32_t kso = (uint32_t)(ks * 32);
#pragma unroll
            for (int mi = 0; mi < 4; mi++) {
                ldm4(ah[mi], aoff_h + (uint32_t)(mi * 16 * TROW * 2) + kso);
                ldm4(al[mi], aoff_l + (uint32_t)(mi * 16 * TROW * 2) + kso);
            }
            ldm4(&bh[0], boff_h + kso);
            ldm4(&bh[4], boff_h + (uint32_t)(16 * TROW * 2) + kso);
#pragma unroll
            for (int mi = 0; mi < 4; mi++)
#pragma unroll
                for (int ni = 0; ni < 4; ni++)
                    mma16816(acc[mi][ni], ah[mi], &bh[ni * 2]);
#pragma unroll
            for (int mi = 0; mi < 4; mi++)
#pragma unroll
                for (int ni = 0; ni < 4; ni++)
                    mma16816(acc[mi][ni], al[mi], &bh[ni * 2]);
            ldm4(&bl[0], boff_l + kso);
            ldm4(&bl[4], boff_l + (uint32_t)(16 * TROW * 2) + kso);
#pragma unroll
            for (int mi = 0; mi < 4; mi++)
#pragma unroll
                for (int ni = 0; ni < 4; ni++)
                    mma16816(acc[mi][ni], ah[mi], &bl[ni * 2]);
        }
    }

    // ---- epilogue ----
#pragma unroll
    for (int mi = 0; mi < 4; mi++) {
#pragma unroll
        for (int ni = 0; ni < 4; ni++) {
            int r0 = bm + wm * 64 + mi * 16 + (lane >> 2);
            int c0 = bn + wn * 32 + ni * 8 + ((lane & 3) << 1);
#pragma unroll
            for (int half = 0; half < 2; half++) {
                int gm = r0 + half * 8;
                float v0 = acc[mi][ni][half * 2]     + bias[c0];
                float v1 = acc[mi][ni][half * 2 + 1] + bias[c0 + 1];
                if (EPI == 1) {
                    v0 *= normcdff(v0); v1 *= normcdff(v1);
                    uint32_t hi, lo;
                    bfsplit2(v0, v1, hi, lo);
                    *(uint32_t*)&Chi[(size_t)gm * N + c0] = hi;
                    *(uint32_t*)&Clo[(size_t)gm * N + c0] = lo;
                } else {
                    if (EPI == 2) {
                        v0 += R[(size_t)gm * N + c0];
                        v1 += R[(size_t)gm * N + c0 + 1];
                    }
                    float2 o; o.x = v0; o.y = v1;
                    *(float2*)&C[(size_t)gm * N + c0] = o;
                }
            }
        }
    }
}

// ---------------- RoPE trig tables (double precision; fast-math-proof) ----------------
__global__ void trig_kernel(float* __restrict__ ct, float* __restrict__ st) {
    int i = blockIdx.x * 256 + threadIdx.x;
    if (i >= TT * 32) return;
    int t = i >> 5, p = i & 31;
    double inv = exp2(-13.287712379549449 * ((double)(2 * p) * (1.0 / 64.0)));
    float invf = (float)inv;
    float angf = (float)((double)t * (double)invf);
    double c, s;
    sincos((double)angf, &s, &c);
    ct[i] = (float)c;
    st[i] = (float)s;
}

// ---------------- embedding ----------------
__global__ void embed_kernel(const int* __restrict__ act, const int* __restrict__ obs,
                             const float* __restrict__ aemb, const float* __restrict__ oemb,
                             const float* __restrict__ temb, float* __restrict__ x) {
    int idx = blockIdx.x * blockDim.x + threadIdx.x;
    if (idx >= BT * DD) return;
    int r = idx / DD, d = idx % DD;
    x[idx] = aemb[(size_t)act[r] * DD + d] + temb[d]
           + oemb[(size_t)obs[r] * DD + d] + temb[DD + d];
}

// ---------------- layernorm -> split bf16 hi/lo directly ----------------
__global__ void ln_kernel(const float* __restrict__ x, const float* __restrict__ g,
                          const float* __restrict__ b, __nv_bfloat16* __restrict__ yh,
                          __nv_bfloat16* __restrict__ yl) {
    int r = blockIdx.x;
    const float* xr = x + (size_t)r * DD;
    float v[4];
    float s = 0.f, ss = 0.f;
#pragma unroll
    for (int i = 0; i < 4; i++) {
        float t = xr[threadIdx.x + i * 256];
        v[i] = t; s += t; ss += t * t;
    }
#pragma unroll
    for (int o = 16; o > 0; o >>= 1) {
        s  += __shfl_xor_sync(0xffffffffu, s,  o);
        ss += __shfl_xor_sync(0xffffffffu, ss, o);
    }
    __shared__ float rs[8], rss[8];
    int w = threadIdx.x >> 5;
    if ((threadIdx.x & 31) == 0) { rs[w] = s; rss[w] = ss; }
    __syncthreads();
    if (threadIdx.x == 0) {
        float a = 0.f, c = 0.f;
#pragma unroll
        for (int i = 0; i < 8; i++) { a += rs[i]; c += rss[i]; }
        rs[0] = a; rss[0] = c;
    }
    __syncthreads();
    float mean = rs[0] * (1.f / DD);
    float var  = rss[0] * (1.f / DD) - mean * mean;
    float inv  = rsqrtf(var + 1e-5f);
#pragma unroll
    for (int i = 0; i < 4; i++) {
        int d = threadIdx.x + i * 256;
        float val = (v[i] - mean) * inv * g[d] + b[d];
        __nv_bfloat16 h = __float2bfloat16_rn(val);
        yh[(size_t)r * DD + d] = h;
        yl[(size_t)r * DD + d] = __float2bfloat16_rn(val - __bfloat162float(h));
    }
}

// ---------------- RoPE + hi/lo split into per-head layout [bh][t][64] ----------------
__global__ void rope_split_kernel(const float* __restrict__ Q, const float* __restrict__ K,
                                  const float* __restrict__ ct, const float* __restrict__ st,
                                  __nv_bfloat16* __restrict__ qh, __nv_bfloat16* __restrict__ ql,
                                  __nv_bfloat16* __restrict__ kh, __nv_bfloat16* __restrict__ kl) {
    int idx = blockIdx.x * 256 + threadIdx.x;
    if (idx >= BT * (DD / 2)) return;
    int r  = idx >> 9;
    int c2 = idx & 511;
    int hh = c2 >> 5, p = c2 & 31;
    int b = r >> 11, t = r & (TT - 1);
    float c = ct[t * 32 + p];
    float s = st[t * 32 + p];
    size_t ib = (size_t)r * DD + hh * 64 + 2 * p;
    size_t ob = ((size_t)(b * HH + hh) * TT + t) * 64 + 2 * p;

    float q0 = Q[ib], q1 = Q[ib + 1];
    float o0 = q0 * c - q1 * s, o1 = q0 * s + q1 * c;
    __nv_bfloat16 h0 = __float2bfloat16_rn(o0), h1 = __float2bfloat16_rn(o1);
    qh[ob] = h0; qh[ob + 1] = h1;
    ql[ob]     = __float2bfloat16_rn(o0 - __bfloat162float(h0));
    ql[ob + 1] = __float2bfloat16_rn(o1 - __bfloat162float(h1));

    float k0 = K[ib], k1 = K[ib + 1];
    float e0 = k0 * c - k1 * s, e1 = k0 * s + k1 * c;
    __nv_bfloat16 g0 = __float2bfloat16_rn(e0), g1 = __float2bfloat16_rn(e1);
    kh[ob] = g0; kh[ob + 1] = g1;
    kl[ob]     = __float2bfloat16_rn(e0 - __bfloat162float(g0));
    kl[ob + 1] = __float2bfloat16_rn(e1 - __bfloat162float(g1));
}

// ---------------- V split + transpose into [bh][d][t] ----------------
__global__ void vsplit_kernel(const float* __restrict__ V,
                              __nv_bfloat16* __restrict__ vh, __nv_bfloat16* __restrict__ vl) {
    __shared__ float ts[32][33];
    int t0 = blockIdx.x * 32, d0 = blockIdx.y * 32, b = blockIdx.z;
    int tx = threadIdx.x & 31, ty = threadIdx.x >> 5;
#pragma unroll
    for (int i = ty; i < 32; i += 8)
        ts[i][tx] = V[((size_t)b * TT + t0 + i) * DD + d0 + tx];
    __syncthreads();
    int hh = d0 >> 6, dl0 = d0 & 63;
#pragma unroll
    for (int i = ty; i < 32; i += 8) {
        float v = ts[tx][i];
        size_t o = ((size_t)(b * HH + hh) * 64 + dl0 + i) * TT + t0 + tx;
        __nv_bfloat16 h = __float2bfloat16_rn(v);
        vh[o] = h;
        vl[o] = __float2bfloat16_rn(v - __bfloat162float(h));
    }
}

// ================= fused flash attention =================
#define FQ_H 0
#define FQ_L 18432
#define FK_H(st) (36864 + (st)*36864)
#define FK_L(st) (FK_H(st) + 18432)
#define FV_H(st) (110592 + (st)*34816)
#define FV_L(st) (FV_H(st) + 17408)
#define FSMEM 180224

__global__ __launch_bounds__(256)
void flash_attn(const __nv_bfloat16* __restrict__ Qh, const __nv_bfloat16* __restrict__ Ql,
                const __nv_bfloat16* __restrict__ Kh, const __nv_bfloat16* __restrict__ Kl,
                const __nv_bfloat16* __restrict__ Vh, const __nv_bfloat16* __restrict__ Vl,
                __nv_bfloat16* __restrict__ Oh, __nv_bfloat16* __restrict__ Ol) {
    int qt = gridDim.x - 1 - blockIdx.x;     // largest work first
    int bh = blockIdx.y;
    int b = bh >> 4, hh = bh & 15;
    extern __shared__ __align__(16) char smem[];
    const uint32_t sb = smem_u32(smem);
    int tid = threadIdx.x, lane = tid & 31, w = tid >> 5;

    {
        int row = tid >> 1, segb = (tid & 1) * 4;
        size_t qg = ((size_t)bh * TT + qt * 128 + row) * 64 + segb * 8;
#pragma unroll
        for (int s = 0; s < 4; s++) {
            uint32_t so = (uint32_t)(row * 144 + (segb + s) * 16);
            *(uint4*)(smem + FQ_H + so) = *(const uint4*)(Qh + qg + s * 8);
            *(uint4*)(smem + FQ_L + so) = *(const uint4*)(Ql + qg + s * 8);
        }
    }

    auto issueKV = [&](int kt, int st) {
        int row = tid >> 1, segb = (tid & 1) * 4;
        size_t kg = ((size_t)bh * TT + kt * 128 + row) * 64 + segb * 8;
#pragma unroll
        for (int s = 0; s < 4; s++) {
            uint32_t so = (uint32_t)(row * 144 + (segb + s) * 16);
            CPA(sb + FK_H(st) + so, Kh + kg + s * 8);
            CPA(sb + FK_L(st) + so, Kl + kg + s * 8);
        }
        int vrow = tid >> 2, vsegb = (tid & 3) * 4;
        size_t vg = ((size_t)bh * 64 + vrow) * TT + kt * 128 + vsegb * 8;
#pragma unroll
        for (int s = 0; s < 4; s++) {
            uint32_t so = (uint32_t)(vrow * 272 + (vsegb + s) * 16);
            CPA(sb + FV_H(st) + so, Vh + vg + s * 8);
            CPA(sb + FV_L(st) + so, Vl + vg + s * 8);
        }
        CPC();
    };
    issueKV(0, 0);
    __syncthreads();

    uint32_t qfh[4][4], qfl[4][4];
    {
        int a_row = w * 16 + (lane & 15), a_col = (lane >> 4) << 3;
        uint32_t qa = (uint32_t)(a_row * 144 + a_col * 2);
#pragma unroll
        for (int ks = 0; ks < 4; ks++) {
            ldm4(qfh[ks], sb + FQ_H + qa + ks * 32);
            ldm4(qfl[ks], sb + FQ_L + qa + ks * 32);
        }
    }

    float m0 = -3.0e38f, m1 = -3.0e38f, l0 = 0.f, l1 = 0.f;
    float O[8][4];
#pragma unroll
    for (int i = 0; i < 8; i++)
#pragma unroll
        for (int z = 0; z < 4; z++) O[i][z] = 0.f;

    int b_rowi = ((lane >> 4) << 3) + (lane & 7);
    int b_colb = (((lane >> 3) & 1) << 3) * 2;   // bytes

    for (int kt = 0; kt <= qt; kt++) {
        if (kt < qt) { issueKV(kt + 1, (kt + 1) & 1); CPW(1); }
        else         { CPW(0); }
        __syncthreads();
        uint32_t kb_h = sb + FK_H(kt & 1), kb_l = sb + FK_L(kt & 1);
        uint32_t vb_h = sb + FV_H(kt & 1), vb_l = sb + FV_L(kt & 1);

        float P[16][4];
#pragma unroll
        for (int i = 0; i < 16; i++)
#pragma unroll
            for (int z = 0; z < 4; z++) P[i][z] = 0.f;
#pragma unroll
        for (int ks = 0; ks < 4; ks++) {
            uint32_t kso = (uint32_t)(ks * 32);
#pragma unroll
            for (int nb = 0; nb < 8; nb++) {
                uint32_t addr = (uint32_t)((nb * 16 + b_rowi) * 144) + b_colb + kso;
                uint32_t kf[4], kfl[4];
                ldm4(kf, kb_h + addr);
                mma16816(P[2*nb],   qfh[ks], &kf[0]);
                mma16816(P[2*nb+1], qfh[ks], &kf[2]);
                mma16816(P[2*nb],   qfl[ks], &kf[0]);
                mma16816(P[2*nb+1], qfl[ks], &kf[2]);
                ldm4(kfl, kb_l + addr);
                mma16816(P[2*nb],   qfh[ks], &kfl[0]);
                mma16816(P[2*nb+1], qfh[ks], &kfl[2]);
            }
        }
#pragma unroll
        for (int i = 0; i < 16; i++)
#pragma unroll
            for (int z = 0; z < 4; z++) P[i][z] *= 0.125f;
        if (kt == qt) {
            int r0 = w * 16 + (lane >> 2);
#pragma unroll
            for (int i = 0; i < 16; i++) {
#pragma unroll
                for (int z = 0; z < 4; z++) {
                    int col = i * 8 + ((lane & 3) << 1) + (z & 1);
                    int row = r0 + ((z >> 1) << 3);
                    if (col > row) P[i][z] = -3.0e38f;
                }
            }
        }
        float mx0 = -3.0e38f, mx1 = -3.0e38f;
#pragma unroll
        for (int i = 0; i < 16; i++) {
            mx0 = fmaxf(mx0, fmaxf(P[i][0], P[i][1]));
            mx1 = fmaxf(mx1, fmaxf(P[i][2], P[i][3]));
        }
        mx0 = fmaxf(mx0, __shfl_xor_sync(0xffffffffu, mx0, 1));
        mx0 = fmaxf(mx0, __shfl_xor_sync(0xffffffffu, mx0, 2));
        mx1 = fmaxf(mx1, __shfl_xor_sync(0xffffffffu, mx1, 1));
        mx1 = fmaxf(mx1, __shfl_xor_sync(0xffffffffu, mx1, 2));
        float mn0 = fmaxf(m0, mx0), mn1 = fmaxf(m1, mx1);
        float al0 = expf(m0 - mn0), al1 = expf(m1 - mn1);
        m0 = mn0; m1 = mn1;
        float s0 = 0.f, s1 = 0.f;
#pragma unroll
        for (int i = 0; i < 16; i++) {
            P[i][0] = expf(P[i][0] - m0); s0 += P[i][0];
            P[i][1] = expf(P[i][1] - m0); s0 += P[i][1];
            P[i][2] = expf(P[i][2] - m1); s1 += P[i][2];
            P[i][3] = expf(P[i][3] - m1); s1 += P[i][3];
        }
        s0 += __shfl_xor_sync(0xffffffffu, s0, 1);
        s0 += __shfl_xor_sync(0xffffffffu, s0, 2);
        s1 += __shfl_xor_sync(0xffffffffu, s1, 1);
        s1 += __shfl_xor_sync(0xffffffffu, s1, 2);
        l0 = l0 * al0 + s0;
        l1 = l1 * al1 + s1;
#pragma unroll
        for (int i = 0; i < 8; i++) {
            O[i][0] *= al0; O[i][1] *= al0;
            O[i][2] *= al1; O[i][3] *= al1;
        }
#pragma unroll
        for (int ks = 0; ks < 8; ks++) {
            uint32_t pah[4], pal[4];
            bfsplit2(P[2*ks][0],   P[2*ks][1],   pah[0], pal[0]);
            bfsplit2(P[2*ks][2],   P[2*ks][3],   pah[1], pal[1]);
            bfsplit2(P[2*ks+1][0], P[2*ks+1][1], pah[2], pal[2]);
            bfsplit2(P[2*ks+1][2], P[2*ks+1][3], pah[3], pal[3]);
            uint32_t kso = (uint32_t)(ks * 32);
#pragma unroll
            for (int nb = 0; nb < 4; nb++) {
                uint32_t addr = (uint32_t)((nb * 16 + b_rowi) * 272) + b_colb + kso;
                uint32_t vf[4], vfl[4];
                ldm4(vf, vb_h + addr);
                mma16816(O[2*nb],   pah, &vf[0]);
                mma16816(O[2*nb+1], pah, &vf[2]);
                mma16816(O[2*nb],   pal, &vf[0]);
                mma16816(O[2*nb+1], pal, &vf[2]);
                ldm4(vfl, vb_l + addr);
                mma16816(O[2*nb],   pah, &vfl[0]);
                mma16816(O[2*nb+1], pah, &vfl[2]);
            }
        }
        __syncthreads();
    }

    float i0 = 1.f / l0, i1 = 1.f / l1;
    int r0 = qt * 128 + w * 16 + (lane >> 2);
    int c0 = hh * 64 + ((lane & 3) << 1);
#pragma unroll
    for (int nj = 0; nj < 8; nj++) {
        int cc = c0 + nj * 8;
        uint32_t hi, lo;
        bfsplit2(O[nj][0] * i0, O[nj][1] * i0, hi, lo);
        size_t o0 = ((size_t)b * TT + r0) * DD + cc;
        *(uint32_t*)&Oh[o0] = hi;
        *(uint32_t*)&Ol[o0] = lo;
        bfsplit2(O[nj][2] * i1, O[nj][3] * i1, hi, lo);
        size_t o1 = ((size_t)b * TT + r0 + 8) * DD + cc;
        *(uint32_t*)&Oh[o1] = hi;
        *(uint32_t*)&Ol[o1] = lo;
    }
}

// ---------------- host-side helpers ----------------
static void conv_B(const float* W, __nv_bfloat16* bh, __nv_bfloat16* bl, int K, int N) {
    convT_kernel<<<dim3(N / 32, K / 64), 256>>>(W, bh, bl, K, N);
}
template <int EPI>
static void gemm(const __nv_bfloat16* ah, const __nv_bfloat16* al,
                 const __nv_bfloat16* bh, const __nv_bfloat16* bl,
                 const float* bias, const float* R, float* C,
                 __nv_bfloat16* Chi, __nv_bfloat16* Clo, int M, int N, int K) {
    static bool cfg = false;
    if (!cfg) {
        cudaFuncSetAttribute(gemm_mma<EPI>, cudaFuncAttributeMaxDynamicSharedMemorySize, GSMEM);
        cfg = true;
    }
    gemm_mma<EPI><<<dim3(N / 128, M / 128), 256, GSMEM>>>(ah, al, bh, bl, bias, R, C, Chi, Clo, M, N, K);
}

// ---------------- launch sequence ----------------
extern "C" void kernel_launch(void* const* d_in, const int* in_sizes, int n_in,
                              void* d_out, int out_size) {
    const int*   actions = (const int*)d_in[0];
    const int*   observ  = (const int*)d_in[1];
    const float* aemb    = (const float*)d_in[2];
    const float* oemb    = (const float*)d_in[3];
    const float* temb    = (const float*)d_in[4];
    const float* Wq      = (const float*)d_in[5];
    const float* bq      = (const float*)d_in[6];
    const float* Wk      = (const float*)d_in[7];
    const float* bk      = (const float*)d_in[8];
    const float* Wv      = (const float*)d_in[9];
    const float* bv      = (const float*)d_in[10];
    const float* Wo      = (const float*)d_in[11];
    const float* bo      = (const float*)d_in[12];
    const float* ln1_g   = (const float*)d_in[13];
    const float* ln1_b   = (const float*)d_in[14];
    const float* ln2_g   = (const float*)d_in[15];
    const float* ln2_b   = (const float*)d_in[16];
    const float* W1      = (const float*)d_in[17];
    const float* b1      = (const float*)d_in[18];
    const float* W2      = (const float*)d_in[19];
    const float* b2      = (const float*)d_in[20];
    const float* out_g   = (const float*)d_in[21];
    const float* out_b   = (const float*)d_in[22];
    const float* Wout    = (const float*)d_in[23];
    const float* bout    = (const float*)d_in[24];

    float *x, *q, *k, *v, *ct, *st;
    __nv_bfloat16 *ah, *al, *fh, *fl, *bh, *bl, *qh, *ql, *kh, *kl, *vh, *vl;
    cudaGetSymbolAddress((void**)&x,  g_x);
    cudaGetSymbolAddress((void**)&q,  g_q);
    cudaGetSymbolAddress((void**)&k,  g_k);
    cudaGetSymbolAddress((void**)&v,  g_v);
    cudaGetSymbolAddress((void**)&ct, g_cos);
    cudaGetSymbolAddress((void**)&st, g_sin);
    cudaGetSymbolAddress((void**)&ah, g_ah);
    cudaGetSymbolAddress((void**)&al, g_al);
    cudaGetSymbolAddress((void**)&fh, g_fh);
    cudaGetSymbolAddress((void**)&fl, g_fl);
    cudaGetSymbolAddress((void**)&bh, g_bh);
    cudaGetSymbolAddress((void**)&bl, g_bl);
    cudaGetSymbolAddress((void**)&qh, g_qh);
    cudaGetSymbolAddress((void**)&ql, g_ql);
    cudaGetSymbolAddress((void**)&kh, g_kh);
    cudaGetSymbolAddress((void**)&kl, g_kl);
    cudaGetSymbolAddress((void**)&vh, g_vh);
    cudaGetSymbolAddress((void**)&vl, g_vl);

    static bool fcfg = false;
    if (!fcfg) {
        cudaFuncSetAttribute(flash_attn, cudaFuncAttributeMaxDynamicSharedMemorySize, FSMEM);
        fcfg = true;
    }

    trig_kernel<<<(TT * 32 + 255) / 256, 256>>>(ct, st);
    embed_kernel<<<(BT * DD + 255) / 256, 256>>>(actions, observ, aemb, oemb, temb, x);

    for (int i = 0; i < LL; i++) {
        ln_kernel<<<BT, 256>>>(x, ln1_g + (size_t)i * DD, ln1_b + (size_t)i * DD, ah, al);

        conv_B(Wq + (size_t)i * DD * DD, bh, bl, DD, DD);
        gemm<0>(ah, al, bh, bl, bq + (size_t)i * DD, nullptr, q, nullptr, nullptr, BT, DD, DD);
        conv_B(Wk + (size_t)i * DD * DD, bh, bl, DD, DD);
        gemm<0>(ah, al, bh, bl, bk + (size_t)i * DD, nullptr, k, nullptr, nullptr, BT, DD, DD);
        conv_B(Wv + (size_t)i * DD * DD, bh, bl, DD, DD);
        gemm<0>(ah, al, bh, bl, bv + (size_t)i * DD, nullptr, v, nullptr, nullptr, BT, DD, DD);

        rope_split_kernel<<<(BT * (DD / 2) + 255) / 256, 256>>>(q, k, ct, st, qh, ql, kh, kl);
        vsplit_kernel<<<dim3(TT / 32, DD / 32, BB), 256>>>(v, vh, vl);

        flash_attn<<<dim3(TT / 128, BB * HH), 256, FSMEM>>>(qh, ql, kh, kl, vh, vl, ah, al);

        conv_B(Wo + (size_t)i * DD * DD, bh, bl, DD, DD);
        gemm<2>(ah, al, bh, bl, bo + (size_t)i * DD, x, x, nullptr, nullptr, BT, DD, DD);

        ln_kernel<<<BT, 256>>>(x, ln2_g + (size_t)i * DD, ln2_b + (size_t)i * DD, ah, al);
        conv_B(W1 + (size_t)i * DD * DFF, bh, bl, DD, DFF);
        gemm<1>(ah, al, bh, bl, b1 + (size_t)i * DFF, nullptr, nullptr, fh, fl, BT, DFF, DD);

        conv_B(W2 + (size_t)i * DFF * DD, bh, bl, DFF, DD);
        gemm<2>(fh, fl, bh, bl, b2 + (size_t)i * DD, x, x, nullptr, nullptr, BT, DD, DFF);
    }

    ln_kernel<<<BT, 256>>>(x, out_g, out_b, ah, al);
    conv_B(Wout, bh, bl, DD, OV);
    gemm<0>(ah, al, bh, bl, bout, nullptr, (float*)d_out, nullptr, nullptr, BT, OV, DD);
}